// round 1
// baseline (speedup 1.0000x reference)
#include <cuda_runtime.h>
#include <cuda_bf16.h>
#include <math.h>

// Problem constants
#define DMODEL 768
#define NH     8
#define DH     96
#define NLAYER 6
#define SPAN   512
#define SEQ    512
#define BATCH  8
#define PPOS   1024          // 2*SPAN
#define FF     3072
#define NTOK   (BATCH*SEQ)   // 4096
#define ZBAT   (BATCH*NH)    // 64
#define LN_EPS 1e-7f
#define NEGF   (-3.402823466e38f)

// -------------------- scratch (device globals; no allocation) --------------------
__device__ float g_h  [NTOK*DMODEL];
__device__ float g_q  [NTOK*DMODEL];
__device__ float g_k  [NTOK*DMODEL];
__device__ float g_v  [NTOK*DMODEL];
__device__ float g_ctx[NTOK*DMODEL];
__device__ float g_tmp[NTOK*DMODEL];
__device__ float g_pk [PPOS*DMODEL];
__device__ float g_pq [PPOS*DMODEL];
__device__ float g_s1 [ZBAT*SEQ*SEQ];        // scores, then probs (in place)
__device__ float g_c2p[ZBAT*SEQ*PPOS];
__device__ float g_p2c[ZBAT*SEQ*PPOS];
__device__ float g_ffn[NTOK*FF];

// -------------------- block reductions (256 threads) --------------------
__device__ __forceinline__ float blk_sum256(float v) {
    __shared__ float sh[8];
    __syncthreads();
    for (int o = 16; o > 0; o >>= 1) v += __shfl_down_sync(0xffffffffu, v, o);
    if ((threadIdx.x & 31) == 0) sh[threadIdx.x >> 5] = v;
    __syncthreads();
    if (threadIdx.x == 0) {
        float s = 0.f;
        #pragma unroll
        for (int i = 0; i < 8; i++) s += sh[i];
        sh[0] = s;
    }
    __syncthreads();
    return sh[0];
}

__device__ __forceinline__ float blk_max256(float v) {
    __shared__ float sh[8];
    __syncthreads();
    for (int o = 16; o > 0; o >>= 1) v = fmaxf(v, __shfl_down_sync(0xffffffffu, v, o));
    if ((threadIdx.x & 31) == 0) sh[threadIdx.x >> 5] = v;
    __syncthreads();
    if (threadIdx.x == 0) {
        float s = sh[0];
        #pragma unroll
        for (int i = 1; i < 8; i++) s = fmaxf(s, sh[i]);
        sh[0] = s;
    }
    __syncthreads();
    return sh[0];
}

// -------------------- GEMM NN: C[M,N] = A[M,K] @ W[K,N] + bias, optional gelu --------
// 64x64 tile, BK=16, 256 threads, 4x4 per thread.
__global__ void gemm_nn(const float* __restrict__ A, const float* __restrict__ W,
                        const float* __restrict__ bias, float* __restrict__ C,
                        int M, int N, int K, int act)
{
    __shared__ float As[16][65];
    __shared__ float Bs[16][65];
    const int tid = threadIdx.x;
    const int m0 = blockIdx.y * 64, n0 = blockIdx.x * 64;
    const int rt = tid >> 4, ct = tid & 15;
    float acc[4][4] = {};

    for (int k0 = 0; k0 < K; k0 += 16) {
        {   // A tile 64x16
            int m  = tid >> 2;
            int kb = (tid & 3) * 4;
            const float4 av = *reinterpret_cast<const float4*>(A + (size_t)(m0 + m) * K + k0 + kb);
            As[kb + 0][m] = av.x; As[kb + 1][m] = av.y; As[kb + 2][m] = av.z; As[kb + 3][m] = av.w;
        }
        {   // W tile 16x64
            int k = tid >> 4;
            int n = (tid & 15) * 4;
            const float4 wv = *reinterpret_cast<const float4*>(W + (size_t)(k0 + k) * N + n0 + n);
            Bs[k][n] = wv.x; Bs[k][n + 1] = wv.y; Bs[k][n + 2] = wv.z; Bs[k][n + 3] = wv.w;
        }
        __syncthreads();
        #pragma unroll
        for (int k = 0; k < 16; k++) {
            float ra[4], rb[4];
            #pragma unroll
            for (int i = 0; i < 4; i++) ra[i] = As[k][rt * 4 + i];
            #pragma unroll
            for (int j = 0; j < 4; j++) rb[j] = Bs[k][ct * 4 + j];
            #pragma unroll
            for (int i = 0; i < 4; i++)
                #pragma unroll
                for (int j = 0; j < 4; j++) acc[i][j] = fmaf(ra[i], rb[j], acc[i][j]);
        }
        __syncthreads();
    }
    #pragma unroll
    for (int i = 0; i < 4; i++) {
        int m = m0 + rt * 4 + i;
        #pragma unroll
        for (int j = 0; j < 4; j++) {
            int n = n0 + ct * 4 + j;
            float v = acc[i][j] + bias[n];
            if (act == 1) v = 0.5f * v * (1.0f + erff(v * 0.7071067811865475f));
            C[(size_t)m * N + n] = v;
        }
    }
}

// -------------------- batched GEMM NT: C[z][M,N] = A[z][M,K] @ B[z][N,K]^T -----------
// z = blockIdx.z, b=z/8, h=z%8. K=96 (3 x BK=32). 64x64 tile, 256 threads.
__global__ void gemm_nt_bat(const float* __restrict__ A, const float* __restrict__ B,
                            float* __restrict__ C, int M, int N, int K,
                            int lda, int ldb,
                            long sAb, long sAh, long sBb, long sBh, long sC)
{
    const int z = blockIdx.z;
    const int bb = z >> 3, hh = z & 7;
    const float* Az = A + (size_t)bb * sAb + (size_t)hh * sAh;
    const float* Bz = B + (size_t)bb * sBb + (size_t)hh * sBh;
    float* Cz = C + (size_t)z * sC;

    __shared__ float As[32][65];
    __shared__ float Bs[32][65];
    const int tid = threadIdx.x;
    const int m0 = blockIdx.y * 64, n0 = blockIdx.x * 64;
    const int rt = tid >> 4, ct = tid & 15;
    float acc[4][4] = {};

    for (int k0 = 0; k0 < K; k0 += 32) {
        const int mm = tid >> 2;
        const int kb = (tid & 3) * 8;
        {
            const float* ap = Az + (size_t)(m0 + mm) * lda + k0 + kb;
            float4 a0 = *reinterpret_cast<const float4*>(ap);
            float4 a1 = *reinterpret_cast<const float4*>(ap + 4);
            As[kb + 0][mm] = a0.x; As[kb + 1][mm] = a0.y; As[kb + 2][mm] = a0.z; As[kb + 3][mm] = a0.w;
            As[kb + 4][mm] = a1.x; As[kb + 5][mm] = a1.y; As[kb + 6][mm] = a1.z; As[kb + 7][mm] = a1.w;
        }
        {
            const float* bp = Bz + (size_t)(n0 + mm) * ldb + k0 + kb;
            float4 b0 = *reinterpret_cast<const float4*>(bp);
            float4 b1 = *reinterpret_cast<const float4*>(bp + 4);
            Bs[kb + 0][mm] = b0.x; Bs[kb + 1][mm] = b0.y; Bs[kb + 2][mm] = b0.z; Bs[kb + 3][mm] = b0.w;
            Bs[kb + 4][mm] = b1.x; Bs[kb + 5][mm] = b1.y; Bs[kb + 6][mm] = b1.z; Bs[kb + 7][mm] = b1.w;
        }
        __syncthreads();
        #pragma unroll
        for (int k = 0; k < 32; k++) {
            float ra[4], rb[4];
            #pragma unroll
            for (int i = 0; i < 4; i++) ra[i] = As[k][rt * 4 + i];
            #pragma unroll
            for (int j = 0; j < 4; j++) rb[j] = Bs[k][ct * 4 + j];
            #pragma unroll
            for (int i = 0; i < 4; i++)
                #pragma unroll
                for (int j = 0; j < 4; j++) acc[i][j] = fmaf(ra[i], rb[j], acc[i][j]);
        }
        __syncthreads();
    }
    #pragma unroll
    for (int i = 0; i < 4; i++) {
        int m = m0 + rt * 4 + i;
        #pragma unroll
        for (int j = 0; j < 4; j++) {
            int n = n0 + ct * 4 + j;
            Cz[(size_t)m * N + n] = acc[i][j];
        }
    }
}

// ------------- combine rel-pos biases + mask + softmax (in place over s1) -----------
// grid (SEQ, ZBAT), 256 threads; each thread owns 2 k positions.
__global__ void combine_softmax(float* __restrict__ s1, const float* __restrict__ c2p,
                                const float* __restrict__ p2c, const int* __restrict__ amask)
{
    const int q = blockIdx.x;
    const int z = blockIdx.y;
    const int b = z >> 3;
    const float inv_scale = 0.05892556509887896f;   // 1/sqrt(288)
    float* srow = s1 + ((size_t)z * SEQ + q) * SEQ;
    const float* crow = c2p + ((size_t)z * SEQ + q) * PPOS;
    const float* pz   = p2c + (size_t)z * SEQ * PPOS;
    const int mq = amask[b * SEQ + q];

    float vals[2];
    #pragma unroll
    for (int i = 0; i < 2; i++) {
        int k = threadIdx.x + i * 256;
        int d = q - k + SPAN;                       // in [1,1023], no clip needed
        float s = (srow[k] + crow[d] + pz[(size_t)k * PPOS + d]) * inv_scale;
        int mk = amask[b * SEQ + k];
        vals[i] = (mq * mk > 0) ? s : NEGF;
    }
    float mx = blk_max256(fmaxf(vals[0], vals[1]));
    float e0 = expf(vals[0] - mx);
    float e1 = expf(vals[1] - mx);
    float sum = blk_sum256(e0 + e1);
    float inv = 1.0f / sum;
    srow[threadIdx.x]       = e0 * inv;
    srow[threadIdx.x + 256] = e1 * inv;
}

// ---------------- ctx = probs @ V, written to [b, q, h*96] layout ----------------
// grid (SEQ/8, NH, BATCH), block (96, 8)
__global__ void ctx_gemm(const float* __restrict__ probs, const float* __restrict__ V,
                         float* __restrict__ ctx)
{
    const int b = blockIdx.z, h = blockIdx.y, q0 = blockIdx.x * 8;
    const int d = threadIdx.x, qi = threadIdx.y;
    const int tid = qi * 96 + d;                    // 0..767
    __shared__ float Ps[8][64];
    __shared__ float Vs[64][97];
    const float* pbase = probs + ((size_t)(b * NH + h) * SEQ + q0) * SEQ;
    const float* vbase = V + (size_t)b * SEQ * DMODEL + (size_t)h * DH;
    float acc = 0.f;

    for (int k0 = 0; k0 < SEQ; k0 += 64) {
        if (tid < 512) {
            int qq = tid >> 6, kk = tid & 63;
            Ps[qq][kk] = pbase[(size_t)qq * SEQ + k0 + kk];
        }
        #pragma unroll
        for (int t = 0; t < 8; t++) {
            int idx = tid + t * 768;                // 64*96 = 6144 elems
            int kk = idx / 96, dd = idx % 96;
            Vs[kk][dd] = vbase[(size_t)(k0 + kk) * DMODEL + dd];
        }
        __syncthreads();
        #pragma unroll
        for (int kk = 0; kk < 64; kk++) acc = fmaf(Ps[qi][kk], Vs[kk][d], acc);
        __syncthreads();
    }
    ctx[(size_t)b * SEQ * DMODEL + (size_t)(q0 + qi) * DMODEL + (size_t)h * DH + d] = acc;
}

// ---------------- LayerNorm variants (one block of 256 per row of 768) ----------------
__global__ void embed_ln(const float* __restrict__ x, const float* __restrict__ pos,
                         const float* __restrict__ g, const float* __restrict__ beta,
                         const int* __restrict__ amask, float* __restrict__ out)
{
    const int row = blockIdx.x;                     // b*SEQ + s
    const int s = row & (SEQ - 1);
    float v[3];
    float partial = 0.f;
    #pragma unroll
    for (int i = 0; i < 3; i++) {
        int j = threadIdx.x + i * 256;
        v[i] = x[(size_t)row * DMODEL + j] + pos[(size_t)s * DMODEL + j];
        partial += v[i];
    }
    float mean = blk_sum256(partial) * (1.0f / DMODEL);
    float p2 = 0.f;
    #pragma unroll
    for (int i = 0; i < 3; i++) { float dlt = v[i] - mean; p2 += dlt * dlt; }
    float var = blk_sum256(p2) * (1.0f / DMODEL);
    float rstd = rsqrtf(var + LN_EPS);
    float mf = (float)amask[row];
    #pragma unroll
    for (int i = 0; i < 3; i++) {
        int j = threadIdx.x + i * 256;
        out[(size_t)row * DMODEL + j] = ((v[i] - mean) * rstd * g[j] + beta[j]) * mf;
    }
}

__global__ void add_ln(const float* __restrict__ a, const float* __restrict__ res,
                       const float* __restrict__ g, const float* __restrict__ beta,
                       float* __restrict__ out)
{
    const int row = blockIdx.x;
    float v[3];
    float partial = 0.f;
    #pragma unroll
    for (int i = 0; i < 3; i++) {
        int j = threadIdx.x + i * 256;
        v[i] = a[(size_t)row * DMODEL + j] + res[(size_t)row * DMODEL + j];
        partial += v[i];
    }
    float mean = blk_sum256(partial) * (1.0f / DMODEL);
    float p2 = 0.f;
    #pragma unroll
    for (int i = 0; i < 3; i++) { float dlt = v[i] - mean; p2 += dlt * dlt; }
    float var = blk_sum256(p2) * (1.0f / DMODEL);
    float rstd = rsqrtf(var + LN_EPS);
    #pragma unroll
    for (int i = 0; i < 3; i++) {
        int j = threadIdx.x + i * 256;
        out[(size_t)row * DMODEL + j] = (v[i] - mean) * rstd * g[j] + beta[j];
    }
}

// ==================================== launcher ====================================
extern "C" void kernel_launch(void* const* d_in, const int* in_sizes, int n_in,
                              void* d_out, int out_size)
{
    const float* x       = (const float*)d_in[0];
    const float* pos_emb = (const float*)d_in[1];
    const float* rel_emb = (const float*)d_in[2];
    const float* ln_e_g  = (const float*)d_in[3];
    const float* ln_e_b  = (const float*)d_in[4];
    const float* Wq  = (const float*)d_in[5];
    const float* bq  = (const float*)d_in[6];
    const float* Wk  = (const float*)d_in[7];
    const float* bk  = (const float*)d_in[8];
    const float* Wv  = (const float*)d_in[9];
    const float* bv  = (const float*)d_in[10];
    const float* Wo  = (const float*)d_in[11];
    const float* bo  = (const float*)d_in[12];
    const float* Wpk = (const float*)d_in[13];
    const float* bpk = (const float*)d_in[14];
    const float* Wpq = (const float*)d_in[15];
    const float* bpq = (const float*)d_in[16];
    const float* ln1g = (const float*)d_in[17];
    const float* ln1b = (const float*)d_in[18];
    const float* Wi   = (const float*)d_in[19];
    const float* bi   = (const float*)d_in[20];
    const float* Wo2  = (const float*)d_in[21];
    const float* bo2  = (const float*)d_in[22];
    const float* ln2g = (const float*)d_in[23];
    const float* ln2b = (const float*)d_in[24];
    const int*   amask = (const int*)d_in[25];

    float *h, *q, *k, *v, *ctx, *tmp, *pk, *pq, *s1, *c2p, *p2c, *ffn;
    cudaGetSymbolAddress((void**)&h,   g_h);
    cudaGetSymbolAddress((void**)&q,   g_q);
    cudaGetSymbolAddress((void**)&k,   g_k);
    cudaGetSymbolAddress((void**)&v,   g_v);
    cudaGetSymbolAddress((void**)&ctx, g_ctx);
    cudaGetSymbolAddress((void**)&tmp, g_tmp);
    cudaGetSymbolAddress((void**)&pk,  g_pk);
    cudaGetSymbolAddress((void**)&pq,  g_pq);
    cudaGetSymbolAddress((void**)&s1,  g_s1);
    cudaGetSymbolAddress((void**)&c2p, g_c2p);
    cudaGetSymbolAddress((void**)&p2c, g_p2c);
    cudaGetSymbolAddress((void**)&ffn, g_ffn);

    // embeddings
    embed_ln<<<NTOK, 256>>>(x, pos_emb, ln_e_g, ln_e_b, amask, h);

    const long DD = (long)DMODEL * DMODEL;
    const dim3 gProj(DMODEL / 64, NTOK / 64);       // (12, 64)
    const dim3 gPos (DMODEL / 64, PPOS / 64);       // (12, 16)
    const dim3 gFF1 (FF / 64, NTOK / 64);           // (48, 64)

    for (int l = 0; l < NLAYER; l++) {
        const float* Wql = Wq + (size_t)l * DD;   const float* bql = bq + (size_t)l * DMODEL;
        const float* Wkl = Wk + (size_t)l * DD;   const float* bkl = bk + (size_t)l * DMODEL;
        const float* Wvl = Wv + (size_t)l * DD;   const float* bvl = bv + (size_t)l * DMODEL;
        const float* Wol = Wo + (size_t)l * DD;   const float* bol = bo + (size_t)l * DMODEL;
        const float* Wpkl = Wpk + (size_t)l * DD; const float* bpkl = bpk + (size_t)l * DMODEL;
        const float* Wpql = Wpq + (size_t)l * DD; const float* bpql = bpq + (size_t)l * DMODEL;

        gemm_nn<<<gProj, 256>>>(h, Wql, bql, q, NTOK, DMODEL, DMODEL, 0);
        gemm_nn<<<gProj, 256>>>(h, Wkl, bkl, k, NTOK, DMODEL, DMODEL, 0);
        gemm_nn<<<gProj, 256>>>(h, Wvl, bvl, v, NTOK, DMODEL, DMODEL, 0);
        gemm_nn<<<gPos, 256>>>(rel_emb, Wpkl, bpkl, pk, PPOS, DMODEL, DMODEL, 0);
        gemm_nn<<<gPos, 256>>>(rel_emb, Wpql, bpql, pq, PPOS, DMODEL, DMODEL, 0);

        // scores: Q@K^T  [z][512,512]
        gemm_nt_bat<<<dim3(SEQ / 64, SEQ / 64, ZBAT), 256>>>(
            q, k, s1, SEQ, SEQ, DH, DMODEL, DMODEL,
            (long)SEQ * DMODEL, (long)DH, (long)SEQ * DMODEL, (long)DH, (long)SEQ * SEQ);
        // c2p: Q@PK^T  [z][512,1024]
        gemm_nt_bat<<<dim3(PPOS / 64, SEQ / 64, ZBAT), 256>>>(
            q, pk, c2p, SEQ, PPOS, DH, DMODEL, DMODEL,
            (long)SEQ * DMODEL, (long)DH, 0L, (long)DH, (long)SEQ * PPOS);
        // p2c: K@PQ^T  [z][512,1024]
        gemm_nt_bat<<<dim3(PPOS / 64, SEQ / 64, ZBAT), 256>>>(
            k, pq, p2c, SEQ, PPOS, DH, DMODEL, DMODEL,
            (long)SEQ * DMODEL, (long)DH, 0L, (long)DH, (long)SEQ * PPOS);

        combine_softmax<<<dim3(SEQ, ZBAT), 256>>>(s1, c2p, p2c, amask);

        ctx_gemm<<<dim3(SEQ / 8, NH, BATCH), dim3(96, 8)>>>(s1, v, ctx);

        gemm_nn<<<gProj, 256>>>(ctx, Wol, bol, tmp, NTOK, DMODEL, DMODEL, 0);
        add_ln<<<NTOK, 256>>>(tmp, h, ln1g + (size_t)l * DMODEL, ln1b + (size_t)l * DMODEL, h);

        gemm_nn<<<gFF1, 256>>>(h, Wi + (size_t)l * DMODEL * FF, bi + (size_t)l * FF,
                               ffn, NTOK, FF, DMODEL, 1);
        gemm_nn<<<gProj, 256>>>(ffn, Wo2 + (size_t)l * FF * DMODEL, bo2 + (size_t)l * DMODEL,
                                tmp, NTOK, DMODEL, FF, 0);

        float* outp = (l == NLAYER - 1) ? (float*)d_out : h;
        add_ln<<<NTOK, 256>>>(tmp, h, ln2g + (size_t)l * DMODEL, ln2b + (size_t)l * DMODEL, outp);
    }
}

// round 2
// speedup vs baseline: 3.4359x; 3.4359x over previous
#include <cuda_runtime.h>
#include <cuda_bf16.h>
#include <math.h>
#include <stdint.h>

// Problem constants
#define DMODEL 768
#define NH     8
#define DH     96
#define NLAYER 6
#define SPAN   512
#define SEQ    512
#define BATCH  8
#define PPOS   1024          // 2*SPAN
#define FF     3072
#define NTOK   (BATCH*SEQ)   // 4096
#define ZBAT   (BATCH*NH)    // 64
#define LN_EPS 1e-7f
#define NEGF   (-3.402823466e38f)

// -------------------- scratch (device globals; no allocation) --------------------
__device__ float g_h  [NTOK*DMODEL];
__device__ float g_q  [NTOK*DMODEL];
__device__ float g_k  [NTOK*DMODEL];
__device__ float g_v  [NTOK*DMODEL];
__device__ float g_ctx[NTOK*DMODEL];
__device__ float g_tmp[NTOK*DMODEL];
__device__ float g_pkall[NLAYER*PPOS*DMODEL];
__device__ float g_pqall[NLAYER*PPOS*DMODEL];
__device__ float g_s1  [ZBAT*SEQ*SEQ];       // scores, then probs (in place)
__device__ float g_c2p [ZBAT*SEQ*PPOS];
__device__ float g_p2c [ZBAT*SEQ*PPOS];
__device__ float g_p2cs[ZBAT*SEQ*SEQ];       // skew-transposed p2c gather
__device__ float g_ffn [NTOK*FF];

// -------------------- helpers --------------------
__device__ __forceinline__ float to_tf32(float x) {
    uint32_t u;
    asm("cvt.rna.tf32.f32 %0, %1;" : "=r"(u) : "f"(x));
    return __uint_as_float(u);
}

__device__ __forceinline__ float gelu_f(float x) {
    return 0.5f * x * (1.0f + erff(x * 0.7071067811865475f));
}

__device__ __forceinline__ void mma_tf32(float c[4], const uint32_t a[4], const uint32_t b[2]) {
    asm volatile(
        "mma.sync.aligned.m16n8k8.row.col.f32.tf32.tf32.f32 "
        "{%0,%1,%2,%3},{%4,%5,%6,%7},{%8,%9},{%0,%1,%2,%3};\n"
        : "+f"(c[0]), "+f"(c[1]), "+f"(c[2]), "+f"(c[3])
        : "r"(a[0]), "r"(a[1]), "r"(a[2]), "r"(a[3]), "r"(b[0]), "r"(b[1]));
}

// ============================ TF32 tensor-core GEMM ============================
// C[M,N] = A[M,K] @ B + bias (opt) with opt gelu. BT=false: B is [K,N] row-major.
// BT=true: B is [N,K] row-major (NT GEMM). Batched via blockIdx.z -> (bb,hh).
template<int BM, int BN, int BK, int WM, int WN, int NWARP, bool BT>
__global__ void __launch_bounds__(NWARP*32)
mma_gemm(const float* __restrict__ A, const float* __restrict__ B,
         const float* __restrict__ bias, float* __restrict__ C,
         int K, int lda, int ldb, int ldc,
         long sAb, long sAh, long sBb, long sBh, long sBiasH,
         long sCb, long sCh, int act)
{
    static_assert(BK == 16, "BK must be 16");
    constexpr int THREADS = NWARP * 32;
    constexpr int MI = WM / 16, NI = WN / 8;
    constexpr int WARPS_N = BN / WN;
    constexpr int BSR = BT ? BN : BK;
    constexpr int BSC = BT ? (BK + 4) : (BN + 8);
    constexpr int A_F4 = BM * BK / 4;
    constexpr int A_IT = (A_F4 + THREADS - 1) / THREADS;
    constexpr int B_F4 = BN * BK / 4;
    constexpr int B_IT = (B_F4 + THREADS - 1) / THREADS;
    constexpr int BNF4 = BN / 4;

    const int z = blockIdx.z, bb = z >> 3, hh = z & 7;
    A += (size_t)bb * sAb + (size_t)hh * sAh;
    B += (size_t)bb * sBb + (size_t)hh * sBh;
    C += (size_t)bb * sCb + (size_t)hh * sCh;
    const float* biasp = bias ? (bias + (size_t)hh * sBiasH) : nullptr;

    __shared__ float As[BM][BK + 4];
    __shared__ float Bs[BSR][BSC];

    const int tid = threadIdx.x;
    const int wid = tid >> 5, lane = tid & 31;
    const int g = lane >> 2, tig = lane & 3;
    const int wm0 = (wid / WARPS_N) * WM, wn0 = (wid % WARPS_N) * WN;
    const int m0 = blockIdx.y * BM, n0 = blockIdx.x * BN;

    float acc[MI][NI][4] = {};
    float4 abuf[A_IT], bbuf[B_IT];

    auto ldgA = [&](int k0) {
        #pragma unroll
        for (int i = 0; i < A_IT; i++) {
            int lin = tid + i * THREADS;
            if ((A_F4 % THREADS == 0) || lin < A_F4) {
                int m = lin >> 2, c = lin & 3;
                abuf[i] = *reinterpret_cast<const float4*>(A + (size_t)(m0 + m) * lda + k0 + 4 * c);
            }
        }
    };
    auto ldgB = [&](int k0) {
        #pragma unroll
        for (int i = 0; i < B_IT; i++) {
            int lin = tid + i * THREADS;
            if ((B_F4 % THREADS == 0) || lin < B_F4) {
                if (BT) {
                    int n = lin >> 2, c = lin & 3;
                    bbuf[i] = *reinterpret_cast<const float4*>(B + (size_t)(n0 + n) * ldb + k0 + 4 * c);
                } else {
                    int kk = lin / BNF4, c = lin % BNF4;
                    bbuf[i] = *reinterpret_cast<const float4*>(B + (size_t)(k0 + kk) * ldb + n0 + 4 * c);
                }
            }
        }
    };
    auto stsA = [&]() {
        #pragma unroll
        for (int i = 0; i < A_IT; i++) {
            int lin = tid + i * THREADS;
            if ((A_F4 % THREADS == 0) || lin < A_F4) {
                int m = lin >> 2, c = lin & 3;
                float4 v = abuf[i];
                v.x = to_tf32(v.x); v.y = to_tf32(v.y); v.z = to_tf32(v.z); v.w = to_tf32(v.w);
                *reinterpret_cast<float4*>(&As[m][4 * c]) = v;
            }
        }
    };
    auto stsB = [&]() {
        #pragma unroll
        for (int i = 0; i < B_IT; i++) {
            int lin = tid + i * THREADS;
            if ((B_F4 % THREADS == 0) || lin < B_F4) {
                float4 v = bbuf[i];
                v.x = to_tf32(v.x); v.y = to_tf32(v.y); v.z = to_tf32(v.z); v.w = to_tf32(v.w);
                if (BT) {
                    int n = lin >> 2, c = lin & 3;
                    *reinterpret_cast<float4*>(&Bs[n][4 * c]) = v;
                } else {
                    int kk = lin / BNF4, c = lin % BNF4;
                    *reinterpret_cast<float4*>(&Bs[kk][4 * c]) = v;
                }
            }
        }
    };

    ldgA(0); ldgB(0);
    const int nk = K / BK;
    for (int it = 0; it < nk; it++) {
        stsA(); stsB();
        __syncthreads();
        if (it + 1 < nk) { ldgA((it + 1) * BK); ldgB((it + 1) * BK); }
        #pragma unroll
        for (int kk = 0; kk < 2; kk++) {
            uint32_t af[MI][4], bf[NI][2];
            #pragma unroll
            for (int i = 0; i < MI; i++) {
                int r = wm0 + 16 * i + g;
                af[i][0] = __float_as_uint(As[r    ][8 * kk + tig]);
                af[i][1] = __float_as_uint(As[r + 8][8 * kk + tig]);
                af[i][2] = __float_as_uint(As[r    ][8 * kk + tig + 4]);
                af[i][3] = __float_as_uint(As[r + 8][8 * kk + tig + 4]);
            }
            #pragma unroll
            for (int j = 0; j < NI; j++) {
                int cc = wn0 + 8 * j + g;
                if (BT) {
                    bf[j][0] = __float_as_uint(Bs[cc][8 * kk + tig]);
                    bf[j][1] = __float_as_uint(Bs[cc][8 * kk + tig + 4]);
                } else {
                    bf[j][0] = __float_as_uint(Bs[8 * kk + tig    ][cc]);
                    bf[j][1] = __float_as_uint(Bs[8 * kk + tig + 4][cc]);
                }
            }
            #pragma unroll
            for (int i = 0; i < MI; i++)
                #pragma unroll
                for (int j = 0; j < NI; j++)
                    mma_tf32(acc[i][j], af[i], bf[j]);
        }
        __syncthreads();
    }

    // epilogue
    #pragma unroll
    for (int i = 0; i < MI; i++) {
        int r0 = m0 + wm0 + 16 * i + g;
        #pragma unroll
        for (int j = 0; j < NI; j++) {
            int col = n0 + wn0 + 8 * j + 2 * tig;
            float b0v = biasp ? biasp[col] : 0.f;
            float b1v = biasp ? biasp[col + 1] : 0.f;
            float v0 = acc[i][j][0] + b0v, v1 = acc[i][j][1] + b1v;
            float v2 = acc[i][j][2] + b0v, v3 = acc[i][j][3] + b1v;
            if (act == 1) { v0 = gelu_f(v0); v1 = gelu_f(v1); v2 = gelu_f(v2); v3 = gelu_f(v3); }
            float2 w01 = make_float2(v0, v1), w23 = make_float2(v2, v3);
            *reinterpret_cast<float2*>(C + (size_t)r0 * ldc + col) = w01;
            *reinterpret_cast<float2*>(C + (size_t)(r0 + 8) * ldc + col) = w23;
        }
    }
}

// ------------- skewed transpose: out[z][q][k] = p2c[z][k][q-k+512] -------------
__global__ void skew_p2c(const float* __restrict__ p2c, float* __restrict__ out)
{
    const int z = blockIdx.z, q0 = blockIdx.y * 32, k0 = blockIdx.x * 32;
    __shared__ float sh[32][66];
    const float* pz = p2c + (size_t)z * SEQ * PPOS;
    const int cbase = q0 - k0 + 481;
    for (int lin = threadIdx.x; lin < 32 * 64; lin += 256) {
        int r = lin >> 6, c = lin & 63;
        int col = cbase + c;
        sh[r][c] = (col >= 0 && col < PPOS) ? pz[(size_t)(k0 + r) * PPOS + col] : 0.f;
    }
    __syncthreads();
    float* oz = out + (size_t)z * SEQ * SEQ;
    for (int lin = threadIdx.x; lin < 32 * 32; lin += 256) {
        int qq = lin >> 5, kk = lin & 31;
        oz[(size_t)(q0 + qq) * SEQ + k0 + kk] = sh[kk][qq - kk + 31];
    }
}

// -------------------- block reductions (256 threads) --------------------
__device__ __forceinline__ float blk_sum256(float v) {
    __shared__ float sh[8];
    __syncthreads();
    for (int o = 16; o > 0; o >>= 1) v += __shfl_down_sync(0xffffffffu, v, o);
    if ((threadIdx.x & 31) == 0) sh[threadIdx.x >> 5] = v;
    __syncthreads();
    if (threadIdx.x == 0) {
        float s = 0.f;
        #pragma unroll
        for (int i = 0; i < 8; i++) s += sh[i];
        sh[0] = s;
    }
    __syncthreads();
    return sh[0];
}

__device__ __forceinline__ float blk_max256(float v) {
    __shared__ float sh[8];
    __syncthreads();
    for (int o = 16; o > 0; o >>= 1) v = fmaxf(v, __shfl_down_sync(0xffffffffu, v, o));
    if ((threadIdx.x & 31) == 0) sh[threadIdx.x >> 5] = v;
    __syncthreads();
    if (threadIdx.x == 0) {
        float s = sh[0];
        #pragma unroll
        for (int i = 1; i < 8; i++) s = fmaxf(s, sh[i]);
        sh[0] = s;
    }
    __syncthreads();
    return sh[0];
}

// ------------- combine rel-pos biases + mask + softmax (in place over s1) -----------
__global__ void combine_softmax(float* __restrict__ s1, const float* __restrict__ c2p,
                                const float* __restrict__ p2cs, const int* __restrict__ amask)
{
    const int q = blockIdx.x;
    const int z = blockIdx.y;
    const int b = z >> 3;
    const float inv_scale = 0.05892556509887896f;   // 1/sqrt(288)
    float* srow = s1 + ((size_t)z * SEQ + q) * SEQ;
    const float* crow = c2p + ((size_t)z * SEQ + q) * PPOS;
    const float* prow = p2cs + ((size_t)z * SEQ + q) * SEQ;
    const int mq = amask[b * SEQ + q];

    float vals[2];
    #pragma unroll
    for (int i = 0; i < 2; i++) {
        int k = threadIdx.x + i * 256;
        int d = q - k + SPAN;                       // in [1,1023]
        float s = (srow[k] + crow[d] + prow[k]) * inv_scale;
        int mk = amask[b * SEQ + k];
        vals[i] = (mq * mk > 0) ? s : NEGF;
    }
    float mx = blk_max256(fmaxf(vals[0], vals[1]));
    float e0 = expf(vals[0] - mx);
    float e1 = expf(vals[1] - mx);
    float sum = blk_sum256(e0 + e1);
    float inv = 1.0f / sum;
    srow[threadIdx.x]       = e0 * inv;
    srow[threadIdx.x + 256] = e1 * inv;
}

// ---------------- LayerNorm variants (one block of 256 per row of 768) ----------------
__global__ void embed_ln(const float* __restrict__ x, const float* __restrict__ pos,
                         const float* __restrict__ g, const float* __restrict__ beta,
                         const int* __restrict__ amask, float* __restrict__ out)
{
    const int row = blockIdx.x;
    const int s = row & (SEQ - 1);
    float v[3];
    float partial = 0.f;
    #pragma unroll
    for (int i = 0; i < 3; i++) {
        int j = threadIdx.x + i * 256;
        v[i] = x[(size_t)row * DMODEL + j] + pos[(size_t)s * DMODEL + j];
        partial += v[i];
    }
    float mean = blk_sum256(partial) * (1.0f / DMODEL);
    float p2 = 0.f;
    #pragma unroll
    for (int i = 0; i < 3; i++) { float d = v[i] - mean; p2 += d * d; }
    float var = blk_sum256(p2) * (1.0f / DMODEL);
    float rstd = rsqrtf(var + LN_EPS);
    float mf = (float)amask[row];
    #pragma unroll
    for (int i = 0; i < 3; i++) {
        int j = threadIdx.x + i * 256;
        out[(size_t)row * DMODEL + j] = ((v[i] - mean) * rstd * g[j] + beta[j]) * mf;
    }
}

__global__ void add_ln(const float* __restrict__ a, const float* __restrict__ res,
                       const float* __restrict__ g, const float* __restrict__ beta,
                       float* __restrict__ out)
{
    const int row = blockIdx.x;
    float v[3];
    float partial = 0.f;
    #pragma unroll
    for (int i = 0; i < 3; i++) {
        int j = threadIdx.x + i * 256;
        v[i] = a[(size_t)row * DMODEL + j] + res[(size_t)row * DMODEL + j];
        partial += v[i];
    }
    float mean = blk_sum256(partial) * (1.0f / DMODEL);
    float p2 = 0.f;
    #pragma unroll
    for (int i = 0; i < 3; i++) { float d = v[i] - mean; p2 += d * d; }
    float var = blk_sum256(p2) * (1.0f / DMODEL);
    float rstd = rsqrtf(var + LN_EPS);
    #pragma unroll
    for (int i = 0; i < 3; i++) {
        int j = threadIdx.x + i * 256;
        out[(size_t)row * DMODEL + j] = (v[i] - mean) * rstd * g[j] + beta[j];
    }
}

// ==================================== launcher ====================================
extern "C" void kernel_launch(void* const* d_in, const int* in_sizes, int n_in,
                              void* d_out, int out_size)
{
    const float* x       = (const float*)d_in[0];
    const float* pos_emb = (const float*)d_in[1];
    const float* rel_emb = (const float*)d_in[2];
    const float* ln_e_g  = (const float*)d_in[3];
    const float* ln_e_b  = (const float*)d_in[4];
    const float* Wq  = (const float*)d_in[5];
    const float* bq  = (const float*)d_in[6];
    const float* Wk  = (const float*)d_in[7];
    const float* bk  = (const float*)d_in[8];
    const float* Wv  = (const float*)d_in[9];
    const float* bv  = (const float*)d_in[10];
    const float* Wo  = (const float*)d_in[11];
    const float* bo  = (const float*)d_in[12];
    const float* Wpk = (const float*)d_in[13];
    const float* bpk = (const float*)d_in[14];
    const float* Wpq = (const float*)d_in[15];
    const float* bpq = (const float*)d_in[16];
    const float* ln1g = (const float*)d_in[17];
    const float* ln1b = (const float*)d_in[18];
    const float* Wi   = (const float*)d_in[19];
    const float* bi   = (const float*)d_in[20];
    const float* Wo2  = (const float*)d_in[21];
    const float* bo2  = (const float*)d_in[22];
    const float* ln2g = (const float*)d_in[23];
    const float* ln2b = (const float*)d_in[24];
    const int*   amask = (const int*)d_in[25];

    float *h, *q, *k, *v, *ctx, *tmp, *pkall, *pqall, *s1, *c2p, *p2c, *p2cs, *ffn;
    cudaGetSymbolAddress((void**)&h,   g_h);
    cudaGetSymbolAddress((void**)&q,   g_q);
    cudaGetSymbolAddress((void**)&k,   g_k);
    cudaGetSymbolAddress((void**)&v,   g_v);
    cudaGetSymbolAddress((void**)&ctx, g_ctx);
    cudaGetSymbolAddress((void**)&tmp, g_tmp);
    cudaGetSymbolAddress((void**)&pkall, g_pkall);
    cudaGetSymbolAddress((void**)&pqall, g_pqall);
    cudaGetSymbolAddress((void**)&s1,  g_s1);
    cudaGetSymbolAddress((void**)&c2p, g_c2p);
    cudaGetSymbolAddress((void**)&p2c, g_p2c);
    cudaGetSymbolAddress((void**)&p2cs, g_p2cs);
    cudaGetSymbolAddress((void**)&ffn, g_ffn);

    const long DD = (long)DMODEL * DMODEL;
    const long S2 = (long)SEQ * SEQ;
    const long SP = (long)SEQ * PPOS;
    const long SD = (long)SEQ * DMODEL;
    const long PD = (long)PPOS * DMODEL;

    // embeddings
    embed_ln<<<NTOK, 256>>>(x, pos_emb, ln_e_g, ln_e_b, amask, h);

    // all-layer position projections: z = layer (0..5)
    mma_gemm<128,128,16,64,32,8,false><<<dim3(DMODEL/128, PPOS/128, NLAYER), 256>>>(
        rel_emb, Wpk, bpk, pkall, DMODEL, DMODEL, DMODEL, DMODEL,
        0, 0, 0, DD, DMODEL, 0, PD, 0);
    mma_gemm<128,128,16,64,32,8,false><<<dim3(DMODEL/128, PPOS/128, NLAYER), 256>>>(
        rel_emb, Wpq, bpq, pqall, DMODEL, DMODEL, DMODEL, DMODEL,
        0, 0, 0, DD, DMODEL, 0, PD, 0);

    const dim3 gProj(DMODEL/128, NTOK/128);   // (6, 32)
    const dim3 gFF1 (FF/128, NTOK/128);       // (24, 32)

    for (int l = 0; l < NLAYER; l++) {
        const float* Wql = Wq + (size_t)l*DD;   const float* bql = bq + (size_t)l*DMODEL;
        const float* Wkl = Wk + (size_t)l*DD;   const float* bkl = bk + (size_t)l*DMODEL;
        const float* Wvl = Wv + (size_t)l*DD;   const float* bvl = bv + (size_t)l*DMODEL;
        const float* Wol = Wo + (size_t)l*DD;   const float* bol = bo + (size_t)l*DMODEL;

        mma_gemm<128,128,16,64,32,8,false><<<gProj, 256>>>(
            h, Wql, bql, q, DMODEL, DMODEL, DMODEL, DMODEL, 0,0,0,0,0, 0,0, 0);
        mma_gemm<128,128,16,64,32,8,false><<<gProj, 256>>>(
            h, Wkl, bkl, k, DMODEL, DMODEL, DMODEL, DMODEL, 0,0,0,0,0, 0,0, 0);
        mma_gemm<128,128,16,64,32,8,false><<<gProj, 256>>>(
            h, Wvl, bvl, v, DMODEL, DMODEL, DMODEL, DMODEL, 0,0,0,0,0, 0,0, 0);

        // scores = Q @ K^T  [z][512,512]
        mma_gemm<128,128,16,64,32,8,true><<<dim3(SEQ/128, SEQ/128, ZBAT), 256>>>(
            q, k, nullptr, s1, DH, DMODEL, DMODEL, SEQ,
            SD, DH, SD, DH, 0, 8*S2, S2, 0);
        // c2p = Q @ PK^T  [z][512,1024]
        mma_gemm<128,128,16,64,32,8,true><<<dim3(PPOS/128, SEQ/128, ZBAT), 256>>>(
            q, pkall + (size_t)l*PD, nullptr, c2p, DH, DMODEL, DMODEL, PPOS,
            SD, DH, 0, DH, 0, 8*SP, SP, 0);
        // p2c = K @ PQ^T  [z][512,1024]
        mma_gemm<128,128,16,64,32,8,true><<<dim3(PPOS/128, SEQ/128, ZBAT), 256>>>(
            k, pqall + (size_t)l*PD, nullptr, p2c, DH, DMODEL, DMODEL, PPOS,
            SD, DH, 0, DH, 0, 8*SP, SP, 0);

        skew_p2c<<<dim3(SEQ/32, SEQ/32, ZBAT), 256>>>(p2c, p2cs);
        combine_softmax<<<dim3(SEQ, ZBAT), 256>>>(s1, c2p, p2cs, amask);

        // ctx = probs @ V  -> [b, q, h*96+d]
        mma_gemm<128,96,16,64,32,6,false><<<dim3(1, SEQ/128, ZBAT), 192>>>(
            s1, v, nullptr, ctx, SEQ, SEQ, DMODEL, DMODEL,
            8*S2, S2, SD, DH, 0, SD, DH, 0);

        mma_gemm<128,128,16,64,32,8,false><<<gProj, 256>>>(
            ctx, Wol, bol, tmp, DMODEL, DMODEL, DMODEL, DMODEL, 0,0,0,0,0, 0,0, 0);
        add_ln<<<NTOK, 256>>>(tmp, h, ln1g + (size_t)l*DMODEL, ln1b + (size_t)l*DMODEL, h);

        mma_gemm<128,128,16,64,32,8,false><<<gFF1, 256>>>(
            h, Wi + (size_t)l*DMODEL*FF, bi + (size_t)l*FF, ffn,
            DMODEL, DMODEL, FF, FF, 0,0,0,0,0, 0,0, 1);
        mma_gemm<128,128,16,64,32,8,false><<<gProj, 256>>>(
            ffn, Wo2 + (size_t)l*FF*DMODEL, bo2 + (size_t)l*DMODEL, tmp,
            FF, FF, DMODEL, DMODEL, 0,0,0,0,0, 0,0, 0);

        float* outp = (l == NLAYER - 1) ? (float*)d_out : h;
        add_ln<<<NTOK, 256>>>(tmp, h, ln2g + (size_t)l*DMODEL, ln2b + (size_t)l*DMODEL, outp);
    }
}

// round 4
// speedup vs baseline: 3.9944x; 1.1625x over previous
#include <cuda_runtime.h>
#include <cuda_bf16.h>
#include <math.h>
#include <stdint.h>

// Problem constants
#define DMODEL 768
#define NH     8
#define DH     96
#define NLAYER 6
#define SPAN   512
#define SEQ    512
#define BATCH  8
#define PPOS   1024          // 2*SPAN
#define FF     3072
#define NTOK   (BATCH*SEQ)   // 4096
#define ZBAT   (BATCH*NH)    // 64
#define LN_EPS 1e-7f
#define NEGF   (-3.402823466e38f)
#define D3     (3*DMODEL)    // 2304

// -------------------- scratch (device globals; no allocation) --------------------
__device__ float g_h   [NTOK*DMODEL];
__device__ float g_qkv [NTOK*D3];
__device__ float g_ctx [NTOK*DMODEL];
__device__ float g_tmp [NTOK*DMODEL];
__device__ float g_wqkv[NLAYER*DMODEL*D3];
__device__ float g_bqkv[NLAYER*D3];
__device__ float g_pkall[NLAYER*PPOS*DMODEL];
__device__ float g_pqall[NLAYER*PPOS*DMODEL];
__device__ float g_s1  [ZBAT*SEQ*SEQ];       // scores, then probs (in place)
__device__ float g_c2p [ZBAT*SEQ*PPOS];
__device__ float g_p2c [ZBAT*SEQ*PPOS];
__device__ float g_ffn [NTOK*FF];

// -------------------- helpers --------------------
__device__ __forceinline__ float to_tf32(float x) {
    uint32_t u;
    asm("cvt.rna.tf32.f32 %0, %1;" : "=r"(u) : "f"(x));
    return __uint_as_float(u);
}

__device__ __forceinline__ float gelu_f(float x) {
    return 0.5f * x * (1.0f + erff(x * 0.7071067811865475f));
}

__device__ __forceinline__ void mma_tf32(float c[4], const uint32_t a[4], const uint32_t b[2]) {
    asm volatile(
        "mma.sync.aligned.m16n8k8.row.col.f32.tf32.tf32.f32 "
        "{%0,%1,%2,%3},{%4,%5,%6,%7},{%8,%9},{%0,%1,%2,%3};\n"
        : "+f"(c[0]), "+f"(c[1]), "+f"(c[2]), "+f"(c[3])
        : "r"(a[0]), "r"(a[1]), "r"(a[2]), "r"(a[3]), "r"(b[0]), "r"(b[1]));
}

// ============================ persistent TF32 GEMM ============================
// Per virtual tile T: z = T/tpz, tl = T%tpz.
// band==0: ty = tl/tiles_x, tx = tl%tiles_x
// band==1 (c2p): ty = tl/5, tx = ty + tl%5         (diagonal band [q+1, q+639])
// band==2 (p2c): ty = tl/5, tx = (3-ty) + tl%5     (band [385-k0, 1023-k0])
// BT=false: B is [K,N] row-major; BT=true: B is [N,K] row-major (NT GEMM).
template<int BM, int BN, int BK, int WM, int WN, int NWARP, bool BT>
__global__ void __launch_bounds__(NWARP*32, 512/(NWARP*32))
mma_gemm(const float* __restrict__ A, const float* __restrict__ B,
         const float* __restrict__ bias, float* __restrict__ C,
         int K, int lda, int ldb, int ldc,
         long sAb, long sAh, long sBb, long sBh, long sBiasH,
         long sCb, long sCh, int act,
         int ntiles, int tpz, int tiles_x, int band)
{
    static_assert(BK == 16, "BK must be 16");
    constexpr int THREADS = NWARP * 32;
    constexpr int MI = WM / 16, NI = WN / 8;
    constexpr int WARPS_N = BN / WN;
    constexpr int BSR = BT ? BN : BK;
    constexpr int BSC = BT ? (BK + 4) : (BN + 8);
    constexpr int A_F4 = BM * BK / 4;
    constexpr int A_IT = (A_F4 + THREADS - 1) / THREADS;
    constexpr int B_F4 = BN * BK / 4;
    constexpr int B_IT = (B_F4 + THREADS - 1) / THREADS;
    constexpr int BNF4 = BN / 4;

    __shared__ float As[2][BM][BK + 4];
    __shared__ float Bs[2][BSR][BSC];

    const int tid = threadIdx.x;
    const int wid = tid >> 5, lane = tid & 31;
    const int g = lane >> 2, tig = lane & 3;
    const int wm0 = (wid / WARPS_N) * WM, wn0 = (wid % WARPS_N) * WN;
    const int nk = K / BK;

    for (int T = blockIdx.x; T < ntiles; T += gridDim.x) {
        const int z = T / tpz, tl = T - z * tpz;
        int ty, tx;
        if (band == 0) { ty = tl / tiles_x; tx = tl - ty * tiles_x; }
        else { ty = tl / 5; int rr = tl - ty * 5; tx = (band == 1 ? ty : 3 - ty) + rr; }
        const int m0 = ty * BM, n0 = tx * BN;
        const int bb = z >> 3, hh = z & 7;
        const float* Az = A + (size_t)bb * sAb + (size_t)hh * sAh;
        const float* Bz = B + (size_t)bb * sBb + (size_t)hh * sBh;
        float* Cz = C + (size_t)bb * sCb + (size_t)hh * sCh;
        const float* biasp = bias ? (bias + (size_t)hh * sBiasH) : nullptr;

        float4 abuf[A_IT], bbuf[B_IT];
        float acc[MI][NI][4];
        #pragma unroll
        for (int i = 0; i < MI; i++)
            #pragma unroll
            for (int j = 0; j < NI; j++)
                #pragma unroll
                for (int t = 0; t < 4; t++) acc[i][j][t] = 0.f;

        auto ldgA = [&](int k0) {
            #pragma unroll
            for (int i = 0; i < A_IT; i++) {
                int lin = tid + i * THREADS;
                if ((A_F4 % THREADS == 0) || lin < A_F4) {
                    int m = lin >> 2, c = lin & 3;
                    abuf[i] = *reinterpret_cast<const float4*>(Az + (size_t)(m0 + m) * lda + k0 + 4 * c);
                }
            }
        };
        auto ldgB = [&](int k0) {
            #pragma unroll
            for (int i = 0; i < B_IT; i++) {
                int lin = tid + i * THREADS;
                if ((B_F4 % THREADS == 0) || lin < B_F4) {
                    if (BT) {
                        int n = lin >> 2, c = lin & 3;
                        bbuf[i] = *reinterpret_cast<const float4*>(Bz + (size_t)(n0 + n) * ldb + k0 + 4 * c);
                    } else {
                        int kk = lin / BNF4, c = lin - kk * BNF4;
                        bbuf[i] = *reinterpret_cast<const float4*>(Bz + (size_t)(k0 + kk) * ldb + n0 + 4 * c);
                    }
                }
            }
        };
        auto sts = [&](int buf) {
            #pragma unroll
            for (int i = 0; i < A_IT; i++) {
                int lin = tid + i * THREADS;
                if ((A_F4 % THREADS == 0) || lin < A_F4) {
                    int m = lin >> 2, c = lin & 3;
                    float4 v = abuf[i];
                    v.x = to_tf32(v.x); v.y = to_tf32(v.y); v.z = to_tf32(v.z); v.w = to_tf32(v.w);
                    *reinterpret_cast<float4*>(&As[buf][m][4 * c]) = v;
                }
            }
            #pragma unroll
            for (int i = 0; i < B_IT; i++) {
                int lin = tid + i * THREADS;
                if ((B_F4 % THREADS == 0) || lin < B_F4) {
                    float4 v = bbuf[i];
                    v.x = to_tf32(v.x); v.y = to_tf32(v.y); v.z = to_tf32(v.z); v.w = to_tf32(v.w);
                    if (BT) {
                        int n = lin >> 2, c = lin & 3;
                        *reinterpret_cast<float4*>(&Bs[buf][n][4 * c]) = v;
                    } else {
                        int kk = lin / BNF4, c = lin - kk * BNF4;
                        *reinterpret_cast<float4*>(&Bs[buf][kk][4 * c]) = v;
                    }
                }
            }
        };

        ldgA(0); ldgB(0);
        __syncthreads();          // protect smem from previous tile's readers
        sts(0);
        __syncthreads();
        int cur = 0;
        for (int it = 0; it < nk; it++) {
            if (it + 1 < nk) { ldgA((it + 1) * BK); ldgB((it + 1) * BK); }
            #pragma unroll
            for (int kk = 0; kk < 2; kk++) {
                uint32_t af[MI][4], bf[NI][2];
                #pragma unroll
                for (int i = 0; i < MI; i++) {
                    int r = wm0 + 16 * i + g;
                    af[i][0] = __float_as_uint(As[cur][r    ][8 * kk + tig]);
                    af[i][1] = __float_as_uint(As[cur][r + 8][8 * kk + tig]);
                    af[i][2] = __float_as_uint(As[cur][r    ][8 * kk + tig + 4]);
                    af[i][3] = __float_as_uint(As[cur][r + 8][8 * kk + tig + 4]);
                }
                #pragma unroll
                for (int j = 0; j < NI; j++) {
                    int cc = wn0 + 8 * j + g;
                    if (BT) {
                        bf[j][0] = __float_as_uint(Bs[cur][cc][8 * kk + tig]);
                        bf[j][1] = __float_as_uint(Bs[cur][cc][8 * kk + tig + 4]);
                    } else {
                        bf[j][0] = __float_as_uint(Bs[cur][8 * kk + tig    ][cc]);
                        bf[j][1] = __float_as_uint(Bs[cur][8 * kk + tig + 4][cc]);
                    }
                }
                #pragma unroll
                for (int i = 0; i < MI; i++)
                    #pragma unroll
                    for (int j = 0; j < NI; j++)
                        mma_tf32(acc[i][j], af[i], bf[j]);
            }
            if (it + 1 < nk) { sts(cur ^ 1); __syncthreads(); cur ^= 1; }
        }

        // epilogue
        #pragma unroll
        for (int i = 0; i < MI; i++) {
            int r0 = m0 + wm0 + 16 * i + g;
            #pragma unroll
            for (int j = 0; j < NI; j++) {
                int col = n0 + wn0 + 8 * j + 2 * tig;
                float b0v = biasp ? biasp[col] : 0.f;
                float b1v = biasp ? biasp[col + 1] : 0.f;
                float v0 = acc[i][j][0] + b0v, v1 = acc[i][j][1] + b1v;
                float v2 = acc[i][j][2] + b0v, v3 = acc[i][j][3] + b1v;
                if (act == 1) { v0 = gelu_f(v0); v1 = gelu_f(v1); v2 = gelu_f(v2); v3 = gelu_f(v3); }
                *reinterpret_cast<float2*>(Cz + (size_t)r0 * ldc + col) = make_float2(v0, v1);
                *reinterpret_cast<float2*>(Cz + (size_t)(r0 + 8) * ldc + col) = make_float2(v2, v3);
            }
        }
    }
}

// ---------------- pack Wq|Wk|Wv -> [L][768][2304] and biases -> [L][2304] ----------------
__global__ void pack_qkv(const float* __restrict__ Wq, const float* __restrict__ Wk,
                         const float* __restrict__ Wv, const float* __restrict__ bq,
                         const float* __restrict__ bk, const float* __restrict__ bv,
                         float* __restrict__ W, float* __restrict__ b)
{
    long idx = (long)blockIdx.x * blockDim.x + threadIdx.x;     // float4 units
    const long totW = (long)NLAYER * DMODEL * D3 / 4;
    if (idx < totW) {
        long e = idx * 4;
        int l = (int)(e / ((long)DMODEL * D3));
        long r = e - (long)l * DMODEL * D3;
        int row = (int)(r / D3);
        int col = (int)(r - (long)row * D3);
        const float* src; int c;
        if (col < DMODEL)        { src = Wq; c = col; }
        else if (col < 2*DMODEL) { src = Wk; c = col - DMODEL; }
        else                     { src = Wv; c = col - 2*DMODEL; }
        *reinterpret_cast<float4*>(W + e) =
            *reinterpret_cast<const float4*>(src + ((size_t)l * DMODEL + row) * DMODEL + c);
    }
    if (idx < NLAYER * D3 / 4) {
        long e = idx * 4;
        int l = (int)(e / D3);
        int col = (int)(e - (long)l * D3);
        const float* src; int c;
        if (col < DMODEL)        { src = bq; c = col; }
        else if (col < 2*DMODEL) { src = bk; c = col - DMODEL; }
        else                     { src = bv; c = col - 2*DMODEL; }
        *reinterpret_cast<float4*>(b + e) =
            *reinterpret_cast<const float4*>(src + (size_t)l * DMODEL + c);
    }
}

// -------------------- block reductions (256 threads) --------------------
__device__ __forceinline__ float blk_sum256(float v) {
    __shared__ float sh[8];
    __syncthreads();
    for (int o = 16; o > 0; o >>= 1) v += __shfl_down_sync(0xffffffffu, v, o);
    if ((threadIdx.x & 31) == 0) sh[threadIdx.x >> 5] = v;
    __syncthreads();
    if (threadIdx.x == 0) {
        float s = 0.f;
        #pragma unroll
        for (int i = 0; i < 8; i++) s += sh[i];
        sh[0] = s;
    }
    __syncthreads();
    return sh[0];
}

__device__ __forceinline__ float blk_max256(float v) {
    __shared__ float sh[8];
    __syncthreads();
    for (int o = 16; o > 0; o >>= 1) v = fmaxf(v, __shfl_down_sync(0xffffffffu, v, o));
    if ((threadIdx.x & 31) == 0) sh[threadIdx.x >> 5] = v;
    __syncthreads();
    if (threadIdx.x == 0) {
        float s = sh[0];
        #pragma unroll
        for (int i = 1; i < 8; i++) s = fmaxf(s, sh[i]);
        sh[0] = s;
    }
    __syncthreads();
    return sh[0];
}

// ------------- combine rel-pos biases + mask + softmax (in place over s1) -----------
// grid (SEQ, ZBAT). p2c read is diagonal; sectors fully consumed by adjacent q-blocks (L2 hit).
__global__ void combine_softmax(float* __restrict__ s1, const float* __restrict__ c2p,
                                const float* __restrict__ p2c, const int* __restrict__ amask)
{
    const int q = blockIdx.x;
    const int z = blockIdx.y;
    const int b = z >> 3;
    const float inv_scale = 0.05892556509887896f;   // 1/sqrt(288)
    float* srow = s1 + ((size_t)z * SEQ + q) * SEQ;
    const float* crow = c2p + ((size_t)z * SEQ + q) * PPOS;
    const float* pz   = p2c + (size_t)z * SEQ * PPOS;
    const int mq = amask[b * SEQ + q];

    float vals[2];
    #pragma unroll
    for (int i = 0; i < 2; i++) {
        int k = threadIdx.x + i * 256;
        int d = q - k + SPAN;                       // in [1,1023], inside computed band
        float s = (srow[k] + crow[d] + pz[(size_t)k * PPOS + d]) * inv_scale;
        int mk = amask[b * SEQ + k];
        vals[i] = (mq * mk > 0) ? s : NEGF;
    }
    float mx = blk_max256(fmaxf(vals[0], vals[1]));
    float e0 = expf(vals[0] - mx);
    float e1 = expf(vals[1] - mx);
    float sum = blk_sum256(e0 + e1);
    float inv = 1.0f / sum;
    srow[threadIdx.x]       = e0 * inv;
    srow[threadIdx.x + 256] = e1 * inv;
}

// ---------------- LayerNorm variants (one block of 256 per row of 768) ----------------
__global__ void embed_ln(const float* __restrict__ x, const float* __restrict__ pos,
                         const float* __restrict__ g, const float* __restrict__ beta,
                         const int* __restrict__ amask, float* __restrict__ out)
{
    const int row = blockIdx.x;
    const int s = row & (SEQ - 1);
    float v[3];
    float partial = 0.f;
    #pragma unroll
    for (int i = 0; i < 3; i++) {
        int j = threadIdx.x + i * 256;
        v[i] = x[(size_t)row * DMODEL + j] + pos[(size_t)s * DMODEL + j];
        partial += v[i];
    }
    float mean = blk_sum256(partial) * (1.0f / DMODEL);
    float p2 = 0.f;
    #pragma unroll
    for (int i = 0; i < 3; i++) { float d = v[i] - mean; p2 += d * d; }
    float var = blk_sum256(p2) * (1.0f / DMODEL);
    float rstd = rsqrtf(var + LN_EPS);
    float mf = (float)amask[row];
    #pragma unroll
    for (int i = 0; i < 3; i++) {
        int j = threadIdx.x + i * 256;
        out[(size_t)row * DMODEL + j] = ((v[i] - mean) * rstd * g[j] + beta[j]) * mf;
    }
}

__global__ void add_ln(const float* __restrict__ a, const float* __restrict__ res,
                       const float* __restrict__ g, const float* __restrict__ beta,
                       float* __restrict__ out)
{
    const int row = blockIdx.x;
    float v[3];
    float partial = 0.f;
    #pragma unroll
    for (int i = 0; i < 3; i++) {
        int j = threadIdx.x + i * 256;
        v[i] = a[(size_t)row * DMODEL + j] + res[(size_t)row * DMODEL + j];
        partial += v[i];
    }
    float mean = blk_sum256(partial) * (1.0f / DMODEL);
    float p2 = 0.f;
    #pragma unroll
    for (int i = 0; i < 3; i++) { float d = v[i] - mean; p2 += d * d; }
    float var = blk_sum256(p2) * (1.0f / DMODEL);
    float rstd = rsqrtf(var + LN_EPS);
    #pragma unroll
    for (int i = 0; i < 3; i++) {
        int j = threadIdx.x + i * 256;
        out[(size_t)row * DMODEL + j] = (v[i] - mean) * rstd * g[j] + beta[j];
    }
}

// ==================================== launcher ====================================
static inline int pgrid(int tiles, int cap) { return tiles < cap ? tiles : cap; }

extern "C" void kernel_launch(void* const* d_in, const int* in_sizes, int n_in,
                              void* d_out, int out_size)
{
    const float* x       = (const float*)d_in[0];
    const float* pos_emb = (const float*)d_in[1];
    const float* rel_emb = (const float*)d_in[2];
    const float* ln_e_g  = (const float*)d_in[3];
    const float* ln_e_b  = (const float*)d_in[4];
    const float* Wq  = (const float*)d_in[5];
    const float* bq  = (const float*)d_in[6];
    const float* Wk  = (const float*)d_in[7];
    const float* bk  = (const float*)d_in[8];
    const float* Wv  = (const float*)d_in[9];
    const float* bv  = (const float*)d_in[10];
    const float* Wo  = (const float*)d_in[11];
    const float* bo  = (const float*)d_in[12];
    const float* Wpk = (const float*)d_in[13];
    const float* bpk = (const float*)d_in[14];
    const float* Wpq = (const float*)d_in[15];
    const float* bpq = (const float*)d_in[16];
    const float* ln1g = (const float*)d_in[17];
    const float* ln1b = (const float*)d_in[18];
    const float* Wi   = (const float*)d_in[19];
    const float* bi   = (const float*)d_in[20];
    const float* Wo2  = (const float*)d_in[21];
    const float* bo2  = (const float*)d_in[22];
    const float* ln2g = (const float*)d_in[23];
    const float* ln2b = (const float*)d_in[24];
    const int*   amask = (const int*)d_in[25];

    float *h, *qkv, *ctx, *tmp, *wqkv, *bqkv, *pkall, *pqall, *s1, *c2p, *p2c, *ffn;
    cudaGetSymbolAddress((void**)&h,    g_h);
    cudaGetSymbolAddress((void**)&qkv,  g_qkv);
    cudaGetSymbolAddress((void**)&ctx,  g_ctx);
    cudaGetSymbolAddress((void**)&tmp,  g_tmp);
    cudaGetSymbolAddress((void**)&wqkv, g_wqkv);
    cudaGetSymbolAddress((void**)&bqkv, g_bqkv);
    cudaGetSymbolAddress((void**)&pkall, g_pkall);
    cudaGetSymbolAddress((void**)&pqall, g_pqall);
    cudaGetSymbolAddress((void**)&s1,   g_s1);
    cudaGetSymbolAddress((void**)&c2p,  g_c2p);
    cudaGetSymbolAddress((void**)&p2c,  g_p2c);
    cudaGetSymbolAddress((void**)&ffn,  g_ffn);

    const long DD = (long)DMODEL * DMODEL;
    const long S2 = (long)SEQ * SEQ;
    const long SP = (long)SEQ * PPOS;
    const long SD3 = (long)SEQ * D3;
    const long PD = (long)PPOS * DMODEL;
    const int CAP2 = 296;    // 2 CTAs/SM x 148 (256-thread configs)
    const int CAP4 = 592;    // 4 CTAs/SM x 148 (128-thread config)

    // weight packing + embeddings
    {
        long totW4 = (long)NLAYER * DMODEL * D3 / 4;
        pack_qkv<<<(unsigned)((totW4 + 255) / 256), 256>>>(Wq, Wk, Wv, bq, bk, bv, wqkv, bqkv);
    }
    embed_ln<<<NTOK, 256>>>(x, pos_emb, ln_e_g, ln_e_b, amask, h);

    // all-layer position projections (z = layer): M=1024, N=768 -> 48 tiles/z, 288 total
    mma_gemm<128,128,16,64,32,8,false><<<pgrid(288, CAP2), 256>>>(
        rel_emb, Wpk, bpk, pkall, DMODEL, DMODEL, DMODEL, DMODEL,
        0, 0, 0, DD, DMODEL, 0, PD, 0, 288, 48, 6, 0);
    mma_gemm<128,128,16,64,32,8,false><<<pgrid(288, CAP2), 256>>>(
        rel_emb, Wpq, bpq, pqall, DMODEL, DMODEL, DMODEL, DMODEL,
        0, 0, 0, DD, DMODEL, 0, PD, 0, 288, 48, 6, 0);

    for (int l = 0; l < NLAYER; l++) {
        // fused QKV: [4096,768] @ [768,2304] -> qkv ; 32x18 = 576 tiles
        mma_gemm<128,128,16,64,32,8,false><<<pgrid(576, CAP2), 256>>>(
            h, wqkv + (size_t)l * DMODEL * D3, bqkv + (size_t)l * D3, qkv,
            DMODEL, DMODEL, D3, D3, 0,0,0,0,0, 0,0, 0, 576, 576, 18, 0);

        // scores = Q @ K^T : 16 tiles/z * 64
        mma_gemm<128,128,16,64,32,8,true><<<pgrid(1024, CAP2), 256>>>(
            qkv, qkv + DMODEL, nullptr, s1, DH, D3, D3, SEQ,
            SD3, DH, SD3, DH, 0, 8*S2, S2, 0, 1024, 16, 4, 0);
        // c2p = Q @ PK^T (banded: 20 tiles/z)
        mma_gemm<128,128,16,64,32,8,true><<<pgrid(1280, CAP2), 256>>>(
            qkv, pkall + (size_t)l * PD, nullptr, c2p, DH, D3, DMODEL, PPOS,
            SD3, DH, 0, DH, 0, 8*SP, SP, 0, 1280, 20, 0, 1);
        // p2c = K @ PQ^T (banded)
        mma_gemm<128,128,16,64,32,8,true><<<pgrid(1280, CAP2), 256>>>(
            qkv + DMODEL, pqall + (size_t)l * PD, nullptr, p2c, DH, D3, DMODEL, PPOS,
            SD3, DH, 0, DH, 0, 8*SP, SP, 0, 1280, 20, 0, 2);

        combine_softmax<<<dim3(SEQ, ZBAT), 256>>>(s1, c2p, p2c, amask);

        // ctx = probs @ V -> [b, q, h*96+d] ; 4 tiles/z * 64 = 256
        mma_gemm<128,96,16,64,32,6,false><<<pgrid(256, CAP2), 192>>>(
            s1, qkv + 2*DMODEL, nullptr, ctx, SEQ, SEQ, D3, DMODEL,
            8*S2, S2, SD3, DH, 0, (long)SEQ*DMODEL, DH, 0, 256, 4, 1, 0);

        // attn out proj: 64x128 tiles -> 64*6 = 384 tiles
        mma_gemm<64,128,16,64,32,4,false><<<pgrid(384, CAP4), 128>>>(
            ctx, Wo + (size_t)l*DD, bo + (size_t)l*DMODEL, tmp,
            DMODEL, DMODEL, DMODEL, DMODEL, 0,0,0,0,0, 0,0, 0, 384, 384, 6, 0);
        add_ln<<<NTOK, 256>>>(tmp, h, ln1g + (size_t)l*DMODEL, ln1b + (size_t)l*DMODEL, h);

        // FFN1 (gelu): 32x24 = 768 tiles
        mma_gemm<128,128,16,64,32,8,false><<<pgrid(768, CAP2), 256>>>(
            h, Wi + (size_t)l*DMODEL*FF, bi + (size_t)l*FF, ffn,
            DMODEL, DMODEL, FF, FF, 0,0,0,0,0, 0,0, 1, 768, 768, 24, 0);
        // FFN2: K=3072, 64x128 tiles -> 384 tiles
        mma_gemm<64,128,16,64,32,4,false><<<pgrid(384, CAP4), 128>>>(
            ffn, Wo2 + (size_t)l*FF*DMODEL, bo2 + (size_t)l*DMODEL, tmp,
            FF, FF, DMODEL, DMODEL, 0,0,0,0,0, 0,0, 0, 384, 384, 6, 0);

        float* outp = (l == NLAYER - 1) ? (float*)d_out : h;
        add_ln<<<NTOK, 256>>>(tmp, h, ln2g + (size_t)l*DMODEL, ln2b + (size_t)l*DMODEL, outp);
    }
}

// round 5
// speedup vs baseline: 3.9946x; 1.0000x over previous
#include <cuda_runtime.h>
#include <cuda_bf16.h>
#include <math.h>
#include <stdint.h>

// Problem constants
#define DMODEL 768
#define NH     8
#define DH     96
#define NLAYER 6
#define SPAN   512
#define SEQ    512
#define BATCH  8
#define PPOS   1024          // 2*SPAN
#define FF     3072
#define NTOK   (BATCH*SEQ)   // 4096
#define ZBAT   (BATCH*NH)    // 64
#define LN_EPS 1e-7f
#define NEGF   (-3.402823466e38f)
#define D3     (3*DMODEL)    // 2304

// -------------------- scratch (device globals; no allocation) --------------------
__device__ float g_h   [NTOK*DMODEL];
__device__ float g_qkv [NTOK*D3];
__device__ float g_ctx [NTOK*DMODEL];
__device__ float g_tmp [NTOK*DMODEL];
__device__ float g_wqkv[NLAYER*DMODEL*D3];
__device__ float g_bqkv[NLAYER*D3];
__device__ float g_pkall[NLAYER*PPOS*DMODEL];
__device__ float g_pqall[NLAYER*PPOS*DMODEL];
__device__ float g_s1  [ZBAT*SEQ*SEQ];       // scores, then probs (in place)
__device__ float g_c2p [ZBAT*SEQ*PPOS];
__device__ float g_p2c [ZBAT*SEQ*PPOS];
__device__ float g_ffn [NTOK*FF];

// -------------------- helpers --------------------
__device__ __forceinline__ float to_tf32(float x) {
    uint32_t u;
    asm("cvt.rna.tf32.f32 %0, %1;" : "=r"(u) : "f"(x));
    return __uint_as_float(u);
}

__device__ __forceinline__ float gelu_f(float x) {
    return 0.5f * x * (1.0f + erff(x * 0.7071067811865475f));
}

__device__ __forceinline__ void mma_tf32(float c[4], const uint32_t a[4], const uint32_t b[2]) {
    asm volatile(
        "mma.sync.aligned.m16n8k8.row.col.f32.tf32.tf32.f32 "
        "{%0,%1,%2,%3},{%4,%5,%6,%7},{%8,%9},{%0,%1,%2,%3};\n"
        : "+f"(c[0]), "+f"(c[1]), "+f"(c[2]), "+f"(c[3])
        : "r"(a[0]), "r"(a[1]), "r"(a[2]), "r"(a[3]), "r"(b[0]), "r"(b[1]));
}

// ============================ persistent TF32 GEMM ============================
// Per virtual tile T: z = T/tpz, tl = T%tpz.
// band==0: ty = tl/tiles_x, tx = tl%tiles_x
// band==1 (c2p): ty = tl/5, tx = ty + tl%5         (diagonal band [q+1, q+639])
// band==2 (p2c): ty = tl/5, tx = (3-ty) + tl%5     (band [385-k0, 1023-k0])
// BT=false: B is [K,N] row-major; BT=true: B is [N,K] row-major (NT GEMM).
template<int BM, int BN, int BK, int WM, int WN, int NWARP, bool BT>
__global__ void __launch_bounds__(NWARP*32, 512/(NWARP*32))
mma_gemm(const float* __restrict__ A, const float* __restrict__ B,
         const float* __restrict__ bias, float* __restrict__ C,
         int K, int lda, int ldb, int ldc,
         long sAb, long sAh, long sBb, long sBh, long sBiasH,
         long sCb, long sCh, int act,
         int ntiles, int tpz, int tiles_x, int band)
{
    static_assert(BK == 16, "BK must be 16");
    constexpr int THREADS = NWARP * 32;
    constexpr int MI = WM / 16, NI = WN / 8;
    constexpr int WARPS_N = BN / WN;
    constexpr int BSR = BT ? BN : BK;
    constexpr int BSC = BT ? (BK + 4) : (BN + 8);
    constexpr int A_F4 = BM * BK / 4;
    constexpr int A_IT = (A_F4 + THREADS - 1) / THREADS;
    constexpr int B_F4 = BN * BK / 4;
    constexpr int B_IT = (B_F4 + THREADS - 1) / THREADS;
    constexpr int BNF4 = BN / 4;

    __shared__ float As[2][BM][BK + 4];
    __shared__ float Bs[2][BSR][BSC];

    const int tid = threadIdx.x;
    const int wid = tid >> 5, lane = tid & 31;
    const int g = lane >> 2, tig = lane & 3;
    const int wm0 = (wid / WARPS_N) * WM, wn0 = (wid % WARPS_N) * WN;
    const int nk = K / BK;

    for (int T = blockIdx.x; T < ntiles; T += gridDim.x) {
        const int z = T / tpz, tl = T - z * tpz;
        int ty, tx;
        if (band == 0) { ty = tl / tiles_x; tx = tl - ty * tiles_x; }
        else { ty = tl / 5; int rr = tl - ty * 5; tx = (band == 1 ? ty : 3 - ty) + rr; }
        const int m0 = ty * BM, n0 = tx * BN;
        const int bb = z >> 3, hh = z & 7;
        const float* Az = A + (size_t)bb * sAb + (size_t)hh * sAh;
        const float* Bz = B + (size_t)bb * sBb + (size_t)hh * sBh;
        float* Cz = C + (size_t)bb * sCb + (size_t)hh * sCh;
        const float* biasp = bias ? (bias + (size_t)hh * sBiasH) : nullptr;

        float4 abuf[A_IT], bbuf[B_IT];
        float acc[MI][NI][4];
        #pragma unroll
        for (int i = 0; i < MI; i++)
            #pragma unroll
            for (int j = 0; j < NI; j++)
                #pragma unroll
                for (int t = 0; t < 4; t++) acc[i][j][t] = 0.f;

        auto ldgA = [&](int k0) {
            #pragma unroll
            for (int i = 0; i < A_IT; i++) {
                int lin = tid + i * THREADS;
                if ((A_F4 % THREADS == 0) || lin < A_F4) {
                    int m = lin >> 2, c = lin & 3;
                    abuf[i] = *reinterpret_cast<const float4*>(Az + (size_t)(m0 + m) * lda + k0 + 4 * c);
                }
            }
        };
        auto ldgB = [&](int k0) {
            #pragma unroll
            for (int i = 0; i < B_IT; i++) {
                int lin = tid + i * THREADS;
                if ((B_F4 % THREADS == 0) || lin < B_F4) {
                    if (BT) {
                        int n = lin >> 2, c = lin & 3;
                        bbuf[i] = *reinterpret_cast<const float4*>(Bz + (size_t)(n0 + n) * ldb + k0 + 4 * c);
                    } else {
                        int kk = lin / BNF4, c = lin - kk * BNF4;
                        bbuf[i] = *reinterpret_cast<const float4*>(Bz + (size_t)(k0 + kk) * ldb + n0 + 4 * c);
                    }
                }
            }
        };
        auto sts = [&](int buf) {
            #pragma unroll
            for (int i = 0; i < A_IT; i++) {
                int lin = tid + i * THREADS;
                if ((A_F4 % THREADS == 0) || lin < A_F4) {
                    int m = lin >> 2, c = lin & 3;
                    float4 v = abuf[i];
                    v.x = to_tf32(v.x); v.y = to_tf32(v.y); v.z = to_tf32(v.z); v.w = to_tf32(v.w);
                    *reinterpret_cast<float4*>(&As[buf][m][4 * c]) = v;
                }
            }
            #pragma unroll
            for (int i = 0; i < B_IT; i++) {
                int lin = tid + i * THREADS;
                if ((B_F4 % THREADS == 0) || lin < B_F4) {
                    float4 v = bbuf[i];
                    v.x = to_tf32(v.x); v.y = to_tf32(v.y); v.z = to_tf32(v.z); v.w = to_tf32(v.w);
                    if (BT) {
                        int n = lin >> 2, c = lin & 3;
                        *reinterpret_cast<float4*>(&Bs[buf][n][4 * c]) = v;
                    } else {
                        int kk = lin / BNF4, c = lin - kk * BNF4;
                        *reinterpret_cast<float4*>(&Bs[buf][kk][4 * c]) = v;
                    }
                }
            }
        };

        ldgA(0); ldgB(0);
        __syncthreads();          // protect smem from previous tile's readers
        sts(0);
        __syncthreads();
        int cur = 0;
        for (int it = 0; it < nk; it++) {
            if (it + 1 < nk) { ldgA((it + 1) * BK); ldgB((it + 1) * BK); }
            #pragma unroll
            for (int kk = 0; kk < 2; kk++) {
                uint32_t af[MI][4], bf[NI][2];
                #pragma unroll
                for (int i = 0; i < MI; i++) {
                    int r = wm0 + 16 * i + g;
                    af[i][0] = __float_as_uint(As[cur][r    ][8 * kk + tig]);
                    af[i][1] = __float_as_uint(As[cur][r + 8][8 * kk + tig]);
                    af[i][2] = __float_as_uint(As[cur][r    ][8 * kk + tig + 4]);
                    af[i][3] = __float_as_uint(As[cur][r + 8][8 * kk + tig + 4]);
                }
                #pragma unroll
                for (int j = 0; j < NI; j++) {
                    int cc = wn0 + 8 * j + g;
                    if (BT) {
                        bf[j][0] = __float_as_uint(Bs[cur][cc][8 * kk + tig]);
                        bf[j][1] = __float_as_uint(Bs[cur][cc][8 * kk + tig + 4]);
                    } else {
                        bf[j][0] = __float_as_uint(Bs[cur][8 * kk + tig    ][cc]);
                        bf[j][1] = __float_as_uint(Bs[cur][8 * kk + tig + 4][cc]);
                    }
                }
                #pragma unroll
                for (int i = 0; i < MI; i++)
                    #pragma unroll
                    for (int j = 0; j < NI; j++)
                        mma_tf32(acc[i][j], af[i], bf[j]);
            }
            if (it + 1 < nk) { sts(cur ^ 1); __syncthreads(); cur ^= 1; }
        }

        // epilogue
        #pragma unroll
        for (int i = 0; i < MI; i++) {
            int r0 = m0 + wm0 + 16 * i + g;
            #pragma unroll
            for (int j = 0; j < NI; j++) {
                int col = n0 + wn0 + 8 * j + 2 * tig;
                float b0v = biasp ? biasp[col] : 0.f;
                float b1v = biasp ? biasp[col + 1] : 0.f;
                float v0 = acc[i][j][0] + b0v, v1 = acc[i][j][1] + b1v;
                float v2 = acc[i][j][2] + b0v, v3 = acc[i][j][3] + b1v;
                if (act == 1) { v0 = gelu_f(v0); v1 = gelu_f(v1); v2 = gelu_f(v2); v3 = gelu_f(v3); }
                *reinterpret_cast<float2*>(Cz + (size_t)r0 * ldc + col) = make_float2(v0, v1);
                *reinterpret_cast<float2*>(Cz + (size_t)(r0 + 8) * ldc + col) = make_float2(v2, v3);
            }
        }
    }
}

// ---------------- pack Wq|Wk|Wv -> [L][768][2304] and biases -> [L][2304] ----------------
__global__ void pack_qkv(const float* __restrict__ Wq, const float* __restrict__ Wk,
                         const float* __restrict__ Wv, const float* __restrict__ bq,
                         const float* __restrict__ bk, const float* __restrict__ bv,
                         float* __restrict__ W, float* __restrict__ b)
{
    long idx = (long)blockIdx.x * blockDim.x + threadIdx.x;     // float4 units
    const long totW = (long)NLAYER * DMODEL * D3 / 4;
    if (idx < totW) {
        long e = idx * 4;
        int l = (int)(e / ((long)DMODEL * D3));
        long r = e - (long)l * DMODEL * D3;
        int row = (int)(r / D3);
        int col = (int)(r - (long)row * D3);
        const float* src; int c;
        if (col < DMODEL)        { src = Wq; c = col; }
        else if (col < 2*DMODEL) { src = Wk; c = col - DMODEL; }
        else                     { src = Wv; c = col - 2*DMODEL; }
        *reinterpret_cast<float4*>(W + e) =
            *reinterpret_cast<const float4*>(src + ((size_t)l * DMODEL + row) * DMODEL + c);
    }
    if (idx < NLAYER * D3 / 4) {
        long e = idx * 4;
        int l = (int)(e / D3);
        int col = (int)(e - (long)l * D3);
        const float* src; int c;
        if (col < DMODEL)        { src = bq; c = col; }
        else if (col < 2*DMODEL) { src = bk; c = col - DMODEL; }
        else                     { src = bv; c = col - 2*DMODEL; }
        *reinterpret_cast<float4*>(b + e) =
            *reinterpret_cast<const float4*>(src + (size_t)l * DMODEL + c);
    }
}

// -------------------- block reductions (256 threads) --------------------
__device__ __forceinline__ float blk_sum256(float v) {
    __shared__ float sh[8];
    __syncthreads();
    for (int o = 16; o > 0; o >>= 1) v += __shfl_down_sync(0xffffffffu, v, o);
    if ((threadIdx.x & 31) == 0) sh[threadIdx.x >> 5] = v;
    __syncthreads();
    if (threadIdx.x == 0) {
        float s = 0.f;
        #pragma unroll
        for (int i = 0; i < 8; i++) s += sh[i];
        sh[0] = s;
    }
    __syncthreads();
    return sh[0];
}

__device__ __forceinline__ float blk_max256(float v) {
    __shared__ float sh[8];
    __syncthreads();
    for (int o = 16; o > 0; o >>= 1) v = fmaxf(v, __shfl_down_sync(0xffffffffu, v, o));
    if ((threadIdx.x & 31) == 0) sh[threadIdx.x >> 5] = v;
    __syncthreads();
    if (threadIdx.x == 0) {
        float s = sh[0];
        #pragma unroll
        for (int i = 1; i < 8; i++) s = fmaxf(s, sh[i]);
        sh[0] = s;
    }
    __syncthreads();
    return sh[0];
}

// ------------- combine rel-pos biases + mask + softmax (in place over s1) -----------
// grid (SEQ, ZBAT). p2c read is diagonal; sectors fully consumed by adjacent q-blocks (L2 hit).
__global__ void combine_softmax(float* __restrict__ s1, const float* __restrict__ c2p,
                                const float* __restrict__ p2c, const int* __restrict__ amask)
{
    const int q = blockIdx.x;
    const int z = blockIdx.y;
    const int b = z >> 3;
    const float inv_scale = 0.05892556509887896f;   // 1/sqrt(288)
    float* srow = s1 + ((size_t)z * SEQ + q) * SEQ;
    const float* crow = c2p + ((size_t)z * SEQ + q) * PPOS;
    const float* pz   = p2c + (size_t)z * SEQ * PPOS;
    const int mq = amask[b * SEQ + q];

    float vals[2];
    #pragma unroll
    for (int i = 0; i < 2; i++) {
        int k = threadIdx.x + i * 256;
        int d = q - k + SPAN;                       // in [1,1023], inside computed band
        float s = (srow[k] + crow[d] + pz[(size_t)k * PPOS + d]) * inv_scale;
        int mk = amask[b * SEQ + k];
        vals[i] = (mq * mk > 0) ? s : NEGF;
    }
    float mx = blk_max256(fmaxf(vals[0], vals[1]));
    float e0 = expf(vals[0] - mx);
    float e1 = expf(vals[1] - mx);
    float sum = blk_sum256(e0 + e1);
    float inv = 1.0f / sum;
    srow[threadIdx.x]       = e0 * inv;
    srow[threadIdx.x + 256] = e1 * inv;
}

// ---------------- LayerNorm variants (one block of 256 per row of 768) ----------------
__global__ void embed_ln(const float* __restrict__ x, const float* __restrict__ pos,
                         const float* __restrict__ g, const float* __restrict__ beta,
                         const int* __restrict__ amask, float* __restrict__ out)
{
    const int row = blockIdx.x;
    const int s = row & (SEQ - 1);
    float v[3];
    float partial = 0.f;
    #pragma unroll
    for (int i = 0; i < 3; i++) {
        int j = threadIdx.x + i * 256;
        v[i] = x[(size_t)row * DMODEL + j] + pos[(size_t)s * DMODEL + j];
        partial += v[i];
    }
    float mean = blk_sum256(partial) * (1.0f / DMODEL);
    float p2 = 0.f;
    #pragma unroll
    for (int i = 0; i < 3; i++) { float d = v[i] - mean; p2 += d * d; }
    float var = blk_sum256(p2) * (1.0f / DMODEL);
    float rstd = rsqrtf(var + LN_EPS);
    float mf = (float)amask[row];
    #pragma unroll
    for (int i = 0; i < 3; i++) {
        int j = threadIdx.x + i * 256;
        out[(size_t)row * DMODEL + j] = ((v[i] - mean) * rstd * g[j] + beta[j]) * mf;
    }
}

__global__ void add_ln(const float* __restrict__ a, const float* __restrict__ res,
                       const float* __restrict__ g, const float* __restrict__ beta,
                       float* __restrict__ out)
{
    const int row = blockIdx.x;
    float v[3];
    float partial = 0.f;
    #pragma unroll
    for (int i = 0; i < 3; i++) {
        int j = threadIdx.x + i * 256;
        v[i] = a[(size_t)row * DMODEL + j] + res[(size_t)row * DMODEL + j];
        partial += v[i];
    }
    float mean = blk_sum256(partial) * (1.0f / DMODEL);
    float p2 = 0.f;
    #pragma unroll
    for (int i = 0; i < 3; i++) { float d = v[i] - mean; p2 += d * d; }
    float var = blk_sum256(p2) * (1.0f / DMODEL);
    float rstd = rsqrtf(var + LN_EPS);
    #pragma unroll
    for (int i = 0; i < 3; i++) {
        int j = threadIdx.x + i * 256;
        out[(size_t)row * DMODEL + j] = (v[i] - mean) * rstd * g[j] + beta[j];
    }
}

// ==================================== launcher ====================================
static inline int pgrid(int tiles, int cap) { return tiles < cap ? tiles : cap; }

extern "C" void kernel_launch(void* const* d_in, const int* in_sizes, int n_in,
                              void* d_out, int out_size)
{
    const float* x       = (const float*)d_in[0];
    const float* pos_emb = (const float*)d_in[1];
    const float* rel_emb = (const float*)d_in[2];
    const float* ln_e_g  = (const float*)d_in[3];
    const float* ln_e_b  = (const float*)d_in[4];
    const float* Wq  = (const float*)d_in[5];
    const float* bq  = (const float*)d_in[6];
    const float* Wk  = (const float*)d_in[7];
    const float* bk  = (const float*)d_in[8];
    const float* Wv  = (const float*)d_in[9];
    const float* bv  = (const float*)d_in[10];
    const float* Wo  = (const float*)d_in[11];
    const float* bo  = (const float*)d_in[12];
    const float* Wpk = (const float*)d_in[13];
    const float* bpk = (const float*)d_in[14];
    const float* Wpq = (const float*)d_in[15];
    const float* bpq = (const float*)d_in[16];
    const float* ln1g = (const float*)d_in[17];
    const float* ln1b = (const float*)d_in[18];
    const float* Wi   = (const float*)d_in[19];
    const float* bi   = (const float*)d_in[20];
    const float* Wo2  = (const float*)d_in[21];
    const float* bo2  = (const float*)d_in[22];
    const float* ln2g = (const float*)d_in[23];
    const float* ln2b = (const float*)d_in[24];
    const int*   amask = (const int*)d_in[25];

    float *h, *qkv, *ctx, *tmp, *wqkv, *bqkv, *pkall, *pqall, *s1, *c2p, *p2c, *ffn;
    cudaGetSymbolAddress((void**)&h,    g_h);
    cudaGetSymbolAddress((void**)&qkv,  g_qkv);
    cudaGetSymbolAddress((void**)&ctx,  g_ctx);
    cudaGetSymbolAddress((void**)&tmp,  g_tmp);
    cudaGetSymbolAddress((void**)&wqkv, g_wqkv);
    cudaGetSymbolAddress((void**)&bqkv, g_bqkv);
    cudaGetSymbolAddress((void**)&pkall, g_pkall);
    cudaGetSymbolAddress((void**)&pqall, g_pqall);
    cudaGetSymbolAddress((void**)&s1,   g_s1);
    cudaGetSymbolAddress((void**)&c2p,  g_c2p);
    cudaGetSymbolAddress((void**)&p2c,  g_p2c);
    cudaGetSymbolAddress((void**)&ffn,  g_ffn);

    const long DD = (long)DMODEL * DMODEL;
    const long S2 = (long)SEQ * SEQ;
    const long SP = (long)SEQ * PPOS;
    const long SD3 = (long)SEQ * D3;
    const long PD = (long)PPOS * DMODEL;
    const int CAP2 = 296;    // 2 CTAs/SM x 148 (256-thread configs)
    const int CAP4 = 592;    // 4 CTAs/SM x 148 (128-thread config)

    // weight packing + embeddings
    {
        long totW4 = (long)NLAYER * DMODEL * D3 / 4;
        pack_qkv<<<(unsigned)((totW4 + 255) / 256), 256>>>(Wq, Wk, Wv, bq, bk, bv, wqkv, bqkv);
    }
    embed_ln<<<NTOK, 256>>>(x, pos_emb, ln_e_g, ln_e_b, amask, h);

    // all-layer position projections (z = layer): M=1024, N=768 -> 48 tiles/z, 288 total
    mma_gemm<128,128,16,64,32,8,false><<<pgrid(288, CAP2), 256>>>(
        rel_emb, Wpk, bpk, pkall, DMODEL, DMODEL, DMODEL, DMODEL,
        0, 0, 0, DD, DMODEL, 0, PD, 0, 288, 48, 6, 0);
    mma_gemm<128,128,16,64,32,8,false><<<pgrid(288, CAP2), 256>>>(
        rel_emb, Wpq, bpq, pqall, DMODEL, DMODEL, DMODEL, DMODEL,
        0, 0, 0, DD, DMODEL, 0, PD, 0, 288, 48, 6, 0);

    for (int l = 0; l < NLAYER; l++) {
        // fused QKV: [4096,768] @ [768,2304] -> qkv ; 32x18 = 576 tiles
        mma_gemm<128,128,16,64,32,8,false><<<pgrid(576, CAP2), 256>>>(
            h, wqkv + (size_t)l * DMODEL * D3, bqkv + (size_t)l * D3, qkv,
            DMODEL, DMODEL, D3, D3, 0,0,0,0,0, 0,0, 0, 576, 576, 18, 0);

        // scores = Q @ K^T : 16 tiles/z * 64
        mma_gemm<128,128,16,64,32,8,true><<<pgrid(1024, CAP2), 256>>>(
            qkv, qkv + DMODEL, nullptr, s1, DH, D3, D3, SEQ,
            SD3, DH, SD3, DH, 0, 8*S2, S2, 0, 1024, 16, 4, 0);
        // c2p = Q @ PK^T (banded: 20 tiles/z)
        mma_gemm<128,128,16,64,32,8,true><<<pgrid(1280, CAP2), 256>>>(
            qkv, pkall + (size_t)l * PD, nullptr, c2p, DH, D3, DMODEL, PPOS,
            SD3, DH, 0, DH, 0, 8*SP, SP, 0, 1280, 20, 0, 1);
        // p2c = K @ PQ^T (banded)
        mma_gemm<128,128,16,64,32,8,true><<<pgrid(1280, CAP2), 256>>>(
            qkv + DMODEL, pqall + (size_t)l * PD, nullptr, p2c, DH, D3, DMODEL, PPOS,
            SD3, DH, 0, DH, 0, 8*SP, SP, 0, 1280, 20, 0, 2);

        combine_softmax<<<dim3(SEQ, ZBAT), 256>>>(s1, c2p, p2c, amask);

        // ctx = probs @ V -> [b, q, h*96+d] ; 4 tiles/z * 64 = 256
        mma_gemm<128,96,16,64,32,6,false><<<pgrid(256, CAP2), 192>>>(
            s1, qkv + 2*DMODEL, nullptr, ctx, SEQ, SEQ, D3, DMODEL,
            8*S2, S2, SD3, DH, 0, (long)SEQ*DMODEL, DH, 0, 256, 4, 1, 0);

        // attn out proj: 64x128 tiles -> 64*6 = 384 tiles
        mma_gemm<64,128,16,64,32,4,false><<<pgrid(384, CAP4), 128>>>(
            ctx, Wo + (size_t)l*DD, bo + (size_t)l*DMODEL, tmp,
            DMODEL, DMODEL, DMODEL, DMODEL, 0,0,0,0,0, 0,0, 0, 384, 384, 6, 0);
        add_ln<<<NTOK, 256>>>(tmp, h, ln1g + (size_t)l*DMODEL, ln1b + (size_t)l*DMODEL, h);

        // FFN1 (gelu): 32x24 = 768 tiles
        mma_gemm<128,128,16,64,32,8,false><<<pgrid(768, CAP2), 256>>>(
            h, Wi + (size_t)l*DMODEL*FF, bi + (size_t)l*FF, ffn,
            DMODEL, DMODEL, FF, FF, 0,0,0,0,0, 0,0, 1, 768, 768, 24, 0);
        // FFN2: K=3072, 64x128 tiles -> 384 tiles
        mma_gemm<64,128,16,64,32,4,false><<<pgrid(384, CAP4), 128>>>(
            ffn, Wo2 + (size_t)l*FF*DMODEL, bo2 + (size_t)l*DMODEL, tmp,
            FF, FF, DMODEL, DMODEL, 0,0,0,0,0, 0,0, 0, 384, 384, 6, 0);

        float* outp = (l == NLAYER - 1) ? (float*)d_out : h;
        add_ln<<<NTOK, 256>>>(tmp, h, ln2g + (size_t)l*DMODEL, ln2b + (size_t)l*DMODEL, outp);
    }
}

// round 7
// speedup vs baseline: 5.5200x; 1.3819x over previous
#include <cuda_runtime.h>
#include <cuda_fp16.h>
#include <math.h>
#include <stdint.h>

#define DMODEL 768
#define NH     8
#define DH     96
#define NLAYER 6
#define SPAN   512
#define SEQ    512
#define BATCH  8
#define PPOS   1024
#define FF     3072
#define NTOK   (BATCH*SEQ)
#define ZBAT   (BATCH*NH)
#define LN_EPS 1e-7f
#define NEGF   (-3.402823466e38f)
#define D3     (3*DMODEL)

// -------------------- scratch --------------------
__device__ float g_h   [NTOK*DMODEL];
__device__ float g_qkv [NTOK*D3];
__device__ float g_ctx [NTOK*DMODEL];
__device__ float g_tmp [NTOK*DMODEL];
__device__ float g_wqkv[(size_t)NLAYER*DMODEL*D3];
__device__ float g_bqkv[NLAYER*D3];
__device__ float g_pkall[(size_t)NLAYER*PPOS*DMODEL];
__device__ float g_pqall[(size_t)NLAYER*PPOS*DMODEL];
__device__ float g_s1  [(size_t)ZBAT*SEQ*SEQ];
__device__ float g_c2p [(size_t)ZBAT*SEQ*PPOS];
__device__ float g_p2c [(size_t)ZBAT*SEQ*PPOS];
__device__ float g_ffn [(size_t)NTOK*FF];

// -------------------- helpers --------------------
__device__ __forceinline__ float gelu_f(float x) {
    return 0.5f * x * (1.0f + erff(x * 0.7071067811865475f));
}
__device__ __forceinline__ uint32_t packh2(float lo, float hi) {
    __half2 h = __floats2half2_rn(lo, hi);
    return *reinterpret_cast<uint32_t*>(&h);
}
__device__ __forceinline__ void mma_f16(float c[4], const uint32_t a[4], const uint32_t b[2]) {
    asm volatile(
        "mma.sync.aligned.m16n8k16.row.col.f32.f16.f16.f32 "
        "{%0,%1,%2,%3},{%4,%5,%6,%7},{%8,%9},{%0,%1,%2,%3};\n"
        : "+f"(c[0]), "+f"(c[1]), "+f"(c[2]), "+f"(c[3])
        : "r"(a[0]), "r"(a[1]), "r"(a[2]), "r"(a[3]), "r"(b[0]), "r"(b[1]));
}

// ============================ persistent FP16 mma GEMM ============================
// C[M,N] = A[M,K] @ B + bias (opt), opt gelu.
// BT=false: B is [K,N] row-major. BT=true: B is [N,K] row-major (NT).
// Virtual tiles: T -> z = T/tpz, tl = T%tpz; band mapping for c2p/p2c diagonal blocks.
template<int BM, int BN, int BK, int WM, int WN, int NWARP, bool BT>
__global__ void __launch_bounds__(NWARP*32, 512/(NWARP*32))
mma_gemm(const float* __restrict__ A, const float* __restrict__ B,
         const float* __restrict__ bias, float* __restrict__ C,
         int K, int lda, int ldb, int ldc,
         long sAb, long sAh, long sBb, long sBh, long sBiasH,
         long sCb, long sCh, int act, int ntiles, int tpz, int tiles_x, int band)
{
    static_assert(BK == 16, "BK must be 16");
    constexpr int THREADS = NWARP * 32;
    constexpr int MI = WM / 16, NI = WN / 8;
    constexpr int WARPS_N = BN / WN;
    // A: pair-packed [BM][12] u32 (8 k-pairs + 4 pad). NT-B same shape [BN][12].
    // NN-B: k-interleaved [8][BN+8] u32.
    constexpr int BSR = BT ? BN : 8;
    constexpr int BSC = BT ? 12 : (BN + 8);
    constexpr int A_F4 = BM * 4;                 // one float4 = 4 k-floats
    constexpr int A_IT = (A_F4 + THREADS - 1) / THREADS;
    constexpr int B_U  = BT ? (BN * 4) : (8 * (BN / 4));
    constexpr int B_IT = (B_U + THREADS - 1) / THREADS;
    constexpr int BN4  = BN / 4;

    __shared__ uint32_t As[2][BM][12];
    __shared__ uint32_t Bs[2][BSR][BSC];

    const int tid = threadIdx.x;
    const int wid = tid >> 5, lane = tid & 31;
    const int g = lane >> 2, tig = lane & 3;
    const int wm0 = (wid / WARPS_N) * WM, wn0 = (wid % WARPS_N) * WN;
    const int nk = K / BK;

    for (int T = blockIdx.x; T < ntiles; T += gridDim.x) {
        const int z = T / tpz, tl = T - z * tpz;
        int ty, tx;
        if (band == 0) { ty = tl / tiles_x; tx = tl - ty * tiles_x; }
        else { ty = tl / 5; int rr = tl - ty * 5; tx = (band == 1 ? ty : 3 - ty) + rr; }
        const int m0 = ty * BM, n0 = tx * BN;
        const int bb = z >> 3, hh = z & 7;
        const float* Az = A + (size_t)bb * sAb + (size_t)hh * sAh;
        const float* Bz = B + (size_t)bb * sBb + (size_t)hh * sBh;
        float* Cz = C + (size_t)bb * sCb + (size_t)hh * sCh;
        const float* biasp = bias ? (bias + (size_t)hh * sBiasH) : nullptr;

        float4 abuf[A_IT], bbuf0[B_IT], bbuf1[B_IT];
        float acc[MI][NI][4];
        #pragma unroll
        for (int i = 0; i < MI; i++)
            #pragma unroll
            for (int j = 0; j < NI; j++)
                #pragma unroll
                for (int t = 0; t < 4; t++) acc[i][j][t] = 0.f;

        auto ldgA = [&](int k0) {
            #pragma unroll
            for (int i = 0; i < A_IT; i++) {
                int lin = tid + i * THREADS;
                if ((A_F4 % THREADS == 0) || lin < A_F4) {
                    int m = lin >> 2, c = lin & 3;
                    abuf[i] = *reinterpret_cast<const float4*>(Az + (size_t)(m0 + m) * lda + k0 + 4 * c);
                }
            }
        };
        auto ldgB = [&](int k0) {
            #pragma unroll
            for (int i = 0; i < B_IT; i++) {
                int lin = tid + i * THREADS;
                if ((B_U % THREADS == 0) || lin < B_U) {
                    if (BT) {
                        int n = lin >> 2, c = lin & 3;
                        bbuf0[i] = *reinterpret_cast<const float4*>(Bz + (size_t)(n0 + n) * ldb + k0 + 4 * c);
                    } else {
                        int kk = lin / BN4, c = lin - kk * BN4;
                        const float* p = Bz + (size_t)(k0 + 2 * kk) * ldb + n0 + 4 * c;
                        bbuf0[i] = *reinterpret_cast<const float4*>(p);
                        bbuf1[i] = *reinterpret_cast<const float4*>(p + ldb);
                    }
                }
            }
        };
        auto stsf = [&](int buf) {
            #pragma unroll
            for (int i = 0; i < A_IT; i++) {
                int lin = tid + i * THREADS;
                if ((A_F4 % THREADS == 0) || lin < A_F4) {
                    int m = lin >> 2, c = lin & 3;
                    float4 v = abuf[i];
                    As[buf][m][2 * c]     = packh2(v.x, v.y);
                    As[buf][m][2 * c + 1] = packh2(v.z, v.w);
                }
            }
            #pragma unroll
            for (int i = 0; i < B_IT; i++) {
                int lin = tid + i * THREADS;
                if ((B_U % THREADS == 0) || lin < B_U) {
                    if (BT) {
                        int n = lin >> 2, c = lin & 3;
                        float4 v = bbuf0[i];
                        Bs[buf][n][2 * c]     = packh2(v.x, v.y);
                        Bs[buf][n][2 * c + 1] = packh2(v.z, v.w);
                    } else {
                        int kk = lin / BN4, c = lin - kk * BN4;
                        float4 v0 = bbuf0[i], v1 = bbuf1[i];
                        Bs[buf][kk][4 * c]     = packh2(v0.x, v1.x);
                        Bs[buf][kk][4 * c + 1] = packh2(v0.y, v1.y);
                        Bs[buf][kk][4 * c + 2] = packh2(v0.z, v1.z);
                        Bs[buf][kk][4 * c + 3] = packh2(v0.w, v1.w);
                    }
                }
            }
        };

        ldgA(0); ldgB(0);
        __syncthreads();          // protect smem from previous tile's readers
        stsf(0);
        __syncthreads();
        int cur = 0;
        for (int it = 0; it < nk; it++) {
            if (it + 1 < nk) { ldgA((it + 1) * BK); ldgB((it + 1) * BK); }
            {
                uint32_t af[MI][4], bf[NI][2];
                #pragma unroll
                for (int i = 0; i < MI; i++) {
                    int r = wm0 + 16 * i + g;
                    af[i][0] = As[cur][r    ][tig];
                    af[i][1] = As[cur][r + 8][tig];
                    af[i][2] = As[cur][r    ][tig + 4];
                    af[i][3] = As[cur][r + 8][tig + 4];
                }
                #pragma unroll
                for (int j = 0; j < NI; j++) {
                    int cc = wn0 + 8 * j + g;
                    if (BT) {
                        bf[j][0] = Bs[cur][cc][tig];
                        bf[j][1] = Bs[cur][cc][tig + 4];
                    } else {
                        bf[j][0] = Bs[cur][tig    ][cc];
                        bf[j][1] = Bs[cur][tig + 4][cc];
                    }
                }
                #pragma unroll
                for (int i = 0; i < MI; i++)
                    #pragma unroll
                    for (int j = 0; j < NI; j++)
                        mma_f16(acc[i][j], af[i], bf[j]);
            }
            if (it + 1 < nk) { stsf(cur ^ 1); __syncthreads(); cur ^= 1; }
        }

        // epilogue
        #pragma unroll
        for (int i = 0; i < MI; i++) {
            int r0 = m0 + wm0 + 16 * i + g;
            #pragma unroll
            for (int j = 0; j < NI; j++) {
                int col = n0 + wn0 + 8 * j + 2 * tig;
                float b0v = biasp ? biasp[col] : 0.f;
                float b1v = biasp ? biasp[col + 1] : 0.f;
                float v0 = acc[i][j][0] + b0v, v1 = acc[i][j][1] + b1v;
                float v2 = acc[i][j][2] + b0v, v3 = acc[i][j][3] + b1v;
                if (act == 1) { v0 = gelu_f(v0); v1 = gelu_f(v1); v2 = gelu_f(v2); v3 = gelu_f(v3); }
                *reinterpret_cast<float2*>(Cz + (size_t)r0 * ldc + col) = make_float2(v0, v1);
                *reinterpret_cast<float2*>(Cz + (size_t)(r0 + 8) * ldc + col) = make_float2(v2, v3);
            }
        }
    }
}

// ---------------- pack Wq|Wk|Wv -> [L][768][2304], biases -> [L][2304] ----------------
__global__ void pack_qkv(const float* __restrict__ Wq, const float* __restrict__ Wk,
                         const float* __restrict__ Wv, const float* __restrict__ bq,
                         const float* __restrict__ bk, const float* __restrict__ bv,
                         float* __restrict__ W, float* __restrict__ b)
{
    long idx = (long)blockIdx.x * blockDim.x + threadIdx.x;     // float4 units
    const long totW = (long)NLAYER * DMODEL * D3 / 4;
    if (idx < totW) {
        long e = idx * 4;
        int l = (int)(e / ((long)DMODEL * D3));
        long r = e - (long)l * DMODEL * D3;
        int row = (int)(r / D3);
        int col = (int)(r - (long)row * D3);
        const float* src; int c;
        if (col < DMODEL)        { src = Wq; c = col; }
        else if (col < 2*DMODEL) { src = Wk; c = col - DMODEL; }
        else                     { src = Wv; c = col - 2*DMODEL; }
        *reinterpret_cast<float4*>(W + e) =
            *reinterpret_cast<const float4*>(src + ((size_t)l * DMODEL + row) * DMODEL + c);
    }
    if (idx < NLAYER * D3 / 4) {
        long e = idx * 4;
        int l = (int)(e / D3);
        int col = (int)(e - (long)l * D3);
        const float* src; int c;
        if (col < DMODEL)        { src = bq; c = col; }
        else if (col < 2*DMODEL) { src = bk; c = col - DMODEL; }
        else                     { src = bv; c = col - 2*DMODEL; }
        *reinterpret_cast<float4*>(b + e) =
            *reinterpret_cast<const float4*>(src + (size_t)l * DMODEL + c);
    }
}

// -------------------- block reductions (256 threads) --------------------
__device__ __forceinline__ float blk_sum256(float v) {
    __shared__ float sh[8];
    __syncthreads();
    for (int o = 16; o > 0; o >>= 1) v += __shfl_down_sync(0xffffffffu, v, o);
    if ((threadIdx.x & 31) == 0) sh[threadIdx.x >> 5] = v;
    __syncthreads();
    if (threadIdx.x == 0) {
        float s = 0.f;
        #pragma unroll
        for (int i = 0; i < 8; i++) s += sh[i];
        sh[0] = s;
    }
    __syncthreads();
    return sh[0];
}
__device__ __forceinline__ float blk_max256(float v) {
    __shared__ float sh[8];
    __syncthreads();
    for (int o = 16; o > 0; o >>= 1) v = fmaxf(v, __shfl_down_sync(0xffffffffu, v, o));
    if ((threadIdx.x & 31) == 0) sh[threadIdx.x >> 5] = v;
    __syncthreads();
    if (threadIdx.x == 0) {
        float s = sh[0];
        #pragma unroll
        for (int i = 1; i < 8; i++) s = fmaxf(s, sh[i]);
        sh[0] = s;
    }
    __syncthreads();
    return sh[0];
}

// ------------- combine rel-pos biases + mask + softmax (in place over s1) -----------
__global__ void combine_softmax(float* __restrict__ s1, const float* __restrict__ c2p,
                                const float* __restrict__ p2c, const int* __restrict__ amask)
{
    const int q = blockIdx.x, z = blockIdx.y, b = z >> 3;
    const float inv_scale = 0.05892556509887896f;   // 1/sqrt(288)
    float* srow = s1 + ((size_t)z * SEQ + q) * SEQ;
    const float* crow = c2p + ((size_t)z * SEQ + q) * PPOS;
    const float* pz   = p2c + (size_t)z * SEQ * PPOS;
    const int mq = amask[b * SEQ + q];
    float vals[2];
    #pragma unroll
    for (int i = 0; i < 2; i++) {
        int k = threadIdx.x + i * 256;
        int d = q - k + SPAN;
        float s = (srow[k] + crow[d] + pz[(size_t)k * PPOS + d]) * inv_scale;
        int mk = amask[b * SEQ + k];
        vals[i] = (mq * mk > 0) ? s : NEGF;
    }
    float mx = blk_max256(fmaxf(vals[0], vals[1]));
    float e0 = expf(vals[0] - mx), e1 = expf(vals[1] - mx);
    float inv = 1.0f / blk_sum256(e0 + e1);
    srow[threadIdx.x]       = e0 * inv;
    srow[threadIdx.x + 256] = e1 * inv;
}

// ---------------- LayerNorm variants ----------------
__global__ void embed_ln(const float* __restrict__ x, const float* __restrict__ pos,
                         const float* __restrict__ g, const float* __restrict__ beta,
                         const int* __restrict__ amask, float* __restrict__ out)
{
    const int row = blockIdx.x, s = row & (SEQ - 1);
    float v[3], partial = 0.f;
    #pragma unroll
    for (int i = 0; i < 3; i++) {
        int j = threadIdx.x + i * 256;
        v[i] = x[(size_t)row * DMODEL + j] + pos[(size_t)s * DMODEL + j];
        partial += v[i];
    }
    float mean = blk_sum256(partial) * (1.0f / DMODEL);
    float p2 = 0.f;
    #pragma unroll
    for (int i = 0; i < 3; i++) { float d = v[i] - mean; p2 += d * d; }
    float rstd = rsqrtf(blk_sum256(p2) * (1.0f / DMODEL) + LN_EPS);
    float mf = (float)amask[row];
    #pragma unroll
    for (int i = 0; i < 3; i++) {
        int j = threadIdx.x + i * 256;
        out[(size_t)row * DMODEL + j] = ((v[i] - mean) * rstd * g[j] + beta[j]) * mf;
    }
}

__global__ void add_ln(const float* __restrict__ a, const float* __restrict__ res,
                       const float* __restrict__ g, const float* __restrict__ beta,
                       float* __restrict__ out)
{
    const int row = blockIdx.x;
    float v[3], partial = 0.f;
    #pragma unroll
    for (int i = 0; i < 3; i++) {
        int j = threadIdx.x + i * 256;
        v[i] = a[(size_t)row * DMODEL + j] + res[(size_t)row * DMODEL + j];
        partial += v[i];
    }
    float mean = blk_sum256(partial) * (1.0f / DMODEL);
    float p2 = 0.f;
    #pragma unroll
    for (int i = 0; i < 3; i++) { float d = v[i] - mean; p2 += d * d; }
    float rstd = rsqrtf(blk_sum256(p2) * (1.0f / DMODEL) + LN_EPS);
    #pragma unroll
    for (int i = 0; i < 3; i++) {
        int j = threadIdx.x + i * 256;
        out[(size_t)row * DMODEL + j] = (v[i] - mean) * rstd * g[j] + beta[j];
    }
}

// ==================================== launcher ====================================
static inline int pgrid(int tiles, int cap) { return tiles < cap ? tiles : cap; }

extern "C" void kernel_launch(void* const* d_in, const int* in_sizes, int n_in,
                              void* d_out, int out_size)
{
    const float* x       = (const float*)d_in[0];
    const float* pos_emb = (const float*)d_in[1];
    const float* rel_emb = (const float*)d_in[2];
    const float* ln_e_g  = (const float*)d_in[3];
    const float* ln_e_b  = (const float*)d_in[4];
    const float* Wq  = (const float*)d_in[5];
    const float* bq  = (const float*)d_in[6];
    const float* Wk  = (const float*)d_in[7];
    const float* bk  = (const float*)d_in[8];
    const float* Wv  = (const float*)d_in[9];
    const float* bv  = (const float*)d_in[10];
    const float* Wo  = (const float*)d_in[11];
    const float* bo  = (const float*)d_in[12];
    const float* Wpk = (const float*)d_in[13];
    const float* bpk = (const float*)d_in[14];
    const float* Wpq = (const float*)d_in[15];
    const float* bpq = (const float*)d_in[16];
    const float* ln1g = (const float*)d_in[17];
    const float* ln1b = (const float*)d_in[18];
    const float* Wi   = (const float*)d_in[19];
    const float* bi   = (const float*)d_in[20];
    const float* Wo2  = (const float*)d_in[21];
    const float* bo2  = (const float*)d_in[22];
    const float* ln2g = (const float*)d_in[23];
    const float* ln2b = (const float*)d_in[24];
    const int*   amask = (const int*)d_in[25];

    float *h, *qkv, *ctx, *tmp, *wqkv, *bqkv, *pkall, *pqall, *s1, *c2p, *p2c, *ffn;
    cudaGetSymbolAddress((void**)&h,    g_h);
    cudaGetSymbolAddress((void**)&qkv,  g_qkv);
    cudaGetSymbolAddress((void**)&ctx,  g_ctx);
    cudaGetSymbolAddress((void**)&tmp,  g_tmp);
    cudaGetSymbolAddress((void**)&wqkv, g_wqkv);
    cudaGetSymbolAddress((void**)&bqkv, g_bqkv);
    cudaGetSymbolAddress((void**)&pkall, g_pkall);
    cudaGetSymbolAddress((void**)&pqall, g_pqall);
    cudaGetSymbolAddress((void**)&s1,   g_s1);
    cudaGetSymbolAddress((void**)&c2p,  g_c2p);
    cudaGetSymbolAddress((void**)&p2c,  g_p2c);
    cudaGetSymbolAddress((void**)&ffn,  g_ffn);

    const long DD = (long)DMODEL * DMODEL;
    const long S2 = (long)SEQ * SEQ;
    const long SP = (long)SEQ * PPOS;
    const long SD3 = (long)SEQ * D3;
    const long PD = (long)PPOS * DMODEL;
    const int CAP2 = 296;    // 2 CTAs/SM x 148 (256-thread configs)
    const int CAP4 = 592;    // 128-thread config

    // weight packing + embeddings
    {
        long totW4 = (long)NLAYER * DMODEL * D3 / 4;
        pack_qkv<<<(unsigned)((totW4 + 255) / 256), 256>>>(Wq, Wk, Wv, bq, bk, bv, wqkv, bqkv);
    }
    embed_ln<<<NTOK, 256>>>(x, pos_emb, ln_e_g, ln_e_b, amask, h);

    // all-layer position projections (z = layer): 48 tiles/z, 288 total
    mma_gemm<128,128,16,64,32,8,false><<<pgrid(288, CAP2), 256>>>(
        rel_emb, Wpk, bpk, pkall, DMODEL, DMODEL, DMODEL, DMODEL,
        0, 0, 0, DD, DMODEL, 0, PD, 0, 288, 48, 6, 0);
    mma_gemm<128,128,16,64,32,8,false><<<pgrid(288, CAP2), 256>>>(
        rel_emb, Wpq, bpq, pqall, DMODEL, DMODEL, DMODEL, DMODEL,
        0, 0, 0, DD, DMODEL, 0, PD, 0, 288, 48, 6, 0);

    for (int l = 0; l < NLAYER; l++) {
        // fused QKV: 32x18 = 576 tiles
        mma_gemm<128,128,16,64,32,8,false><<<pgrid(576, CAP2), 256>>>(
            h, wqkv + (size_t)l * DMODEL * D3, bqkv + (size_t)l * D3, qkv,
            DMODEL, DMODEL, D3, D3, 0,0,0,0,0, 0,0, 0, 576, 576, 18, 0);

        // scores = Q @ K^T : 16 tiles/z * 64
        mma_gemm<128,128,16,64,32,8,true><<<pgrid(1024, CAP2), 256>>>(
            qkv, qkv + DMODEL, nullptr, s1, DH, D3, D3, SEQ,
            SD3, DH, SD3, DH, 0, 8*S2, S2, 0, 1024, 16, 4, 0);
        // c2p = Q @ PK^T (banded: 20 tiles/z)
        mma_gemm<128,128,16,64,32,8,true><<<pgrid(1280, CAP2), 256>>>(
            qkv, pkall + (size_t)l * PD, nullptr, c2p, DH, D3, DMODEL, PPOS,
            SD3, DH, 0, DH, 0, 8*SP, SP, 0, 1280, 20, 0, 1);
        // p2c = K @ PQ^T (banded)
        mma_gemm<128,128,16,64,32,8,true><<<pgrid(1280, CAP2), 256>>>(
            qkv + DMODEL, pqall + (size_t)l * PD, nullptr, p2c, DH, D3, DMODEL, PPOS,
            SD3, DH, 0, DH, 0, 8*SP, SP, 0, 1280, 20, 0, 2);

        combine_softmax<<<dim3(SEQ, ZBAT), 256>>>(s1, c2p, p2c, amask);

        // ctx = probs @ V -> [b, q, h*96+d] ; 4 tiles/z * 64 = 256
        mma_gemm<128,96,16,64,32,6,false><<<pgrid(256, CAP2), 192>>>(
            s1, qkv + 2*DMODEL, nullptr, ctx, SEQ, SEQ, D3, DMODEL,
            8*S2, S2, SD3, DH, 0, (long)SEQ*DMODEL, DH, 0, 256, 4, 1, 0);

        // attn out proj: 64x128 tiles -> 384 tiles
        mma_gemm<64,128,16,64,32,4,false><<<pgrid(384, CAP4), 128>>>(
            ctx, Wo + (size_t)l*DD, bo + (size_t)l*DMODEL, tmp,
            DMODEL, DMODEL, DMODEL, DMODEL, 0,0,0,0,0, 0,0, 0, 384, 384, 6, 0);
        add_ln<<<NTOK, 256>>>(tmp, h, ln1g + (size_t)l*DMODEL, ln1b + (size_t)l*DMODEL, h);

        // FFN1 (gelu): 768 tiles
        mma_gemm<128,128,16,64,32,8,false><<<pgrid(768, CAP2), 256>>>(
            h, Wi + (size_t)l*DMODEL*FF, bi + (size_t)l*FF, ffn,
            DMODEL, DMODEL, FF, FF, 0,0,0,0,0, 0,0, 1, 768, 768, 24, 0);
        // FFN2: K=3072, 384 tiles
        mma_gemm<64,128,16,64,32,4,false><<<pgrid(384, CAP4), 128>>>(
            ffn, Wo2 + (size_t)l*FF*DMODEL, bo2 + (size_t)l*DMODEL, tmp,
            FF, FF, DMODEL, DMODEL, 0,0,0,0,0, 0,0, 0, 384, 384, 6, 0);

        float* outp = (l == NLAYER - 1) ? (float*)d_out : h;
        add_ln<<<NTOK, 256>>>(tmp, h, ln2g + (size_t)l*DMODEL, ln2b + (size_t)l*DMODEL, outp);
    }
}

// round 8
// speedup vs baseline: 5.7386x; 1.0396x over previous
#include <cuda_runtime.h>
#include <cuda_fp16.h>
#include <math.h>
#include <stdint.h>

#define DMODEL 768
#define NH     8
#define DH     96
#define NLAYER 6
#define SPAN   512
#define SEQ    512
#define BATCH  8
#define PPOS   1024
#define FF     3072
#define NTOK   (BATCH*SEQ)
#define ZBAT   (BATCH*NH)
#define LN_EPS 1e-7f
#define NEGF   (-3.402823466e38f)
#define D3     (3*DMODEL)

// -------------------- scratch --------------------
__device__ float g_h   [NTOK*DMODEL];
__device__ float g_qkv [NTOK*D3];
__device__ float g_ctx [NTOK*DMODEL];
__device__ float g_tmp [NTOK*DMODEL];
__device__ float g_wqkv[(size_t)NLAYER*DMODEL*D3];
__device__ float g_bqkv[NLAYER*D3];
__device__ float g_pkall[(size_t)NLAYER*PPOS*DMODEL];
__device__ float g_pqall[(size_t)NLAYER*PPOS*DMODEL];
__device__ float g_s1  [(size_t)ZBAT*SEQ*SEQ];
__device__ float g_c2p [(size_t)ZBAT*SEQ*PPOS];
__device__ float g_p2c [(size_t)ZBAT*SEQ*PPOS];
__device__ float g_ffn [(size_t)NTOK*FF];

// -------------------- helpers --------------------
__device__ __forceinline__ float gelu_f(float x) {
    return 0.5f * x * (1.0f + erff(x * 0.7071067811865475f));
}
__device__ __forceinline__ uint32_t packh2(float lo, float hi) {
    __half2 h = __floats2half2_rn(lo, hi);
    return *reinterpret_cast<uint32_t*>(&h);
}
__device__ __forceinline__ uint32_t smem_u32(const void* p) {
    uint32_t a;
    asm("{ .reg .u64 t; cvta.to.shared.u64 t, %1; cvt.u32.u64 %0, t; }" : "=r"(a) : "l"(p));
    return a;
}
__device__ __forceinline__ void mma_f16(float c[4], const uint32_t a[4], const uint32_t b[2]) {
    asm volatile(
        "mma.sync.aligned.m16n8k16.row.col.f32.f16.f16.f32 "
        "{%0,%1,%2,%3},{%4,%5,%6,%7},{%8,%9},{%0,%1,%2,%3};\n"
        : "+f"(c[0]), "+f"(c[1]), "+f"(c[2]), "+f"(c[3])
        : "r"(a[0]), "r"(a[1]), "r"(a[2]), "r"(a[3]), "r"(b[0]), "r"(b[1]));
}
__device__ __forceinline__ void ldsm_x4(uint32_t r[4], uint32_t addr) {
    asm volatile("ldmatrix.sync.aligned.m8n8.x4.shared.b16 {%0,%1,%2,%3}, [%4];"
        : "=r"(r[0]), "=r"(r[1]), "=r"(r[2]), "=r"(r[3]) : "r"(addr));
}

// ============================ persistent FP16 mma GEMM ============================
// C[M,N] = A[M,K] @ B + bias (opt), opt gelu.
// BT=false: B is [K,N] row-major. BT=true: B is [N,K] row-major (NT).
// A smem: pair-packed u32 [BM][12] (8 k-pairs + pad) -> ldmatrix.x4 fragments.
// NT-B smem: same shape [BN][12] -> ldmatrix.x4 (2 n-blocks per call).
// NN-B smem: k-interleaved [8][BN+8] -> scalar LDS (layout == b-fragment).
template<int BM, int BN, int BK, int WM, int WN, int NWARP, bool BT>
__global__ void __launch_bounds__(NWARP*32, 512/(NWARP*32))
mma_gemm(const float* __restrict__ A, const float* __restrict__ B,
         const float* __restrict__ bias, float* __restrict__ C,
         int K, int lda, int ldb, int ldc,
         long sAb, long sAh, long sBb, long sBh, long sBiasH,
         long sCb, long sCh, int act, int ntiles, int tpz, int tiles_x, int band)
{
    static_assert(BK == 16, "BK must be 16");
    constexpr int THREADS = NWARP * 32;
    constexpr int MI = WM / 16, NI = WN / 8;
    constexpr int WARPS_N = BN / WN;
    constexpr int BSR = BT ? BN : 8;
    constexpr int BSC = BT ? 12 : (BN + 8);
    constexpr int A_F4 = BM * 4;
    constexpr int A_IT = (A_F4 + THREADS - 1) / THREADS;
    constexpr int B_U  = BT ? (BN * 4) : (8 * (BN / 4));
    constexpr int B_IT = (B_U + THREADS - 1) / THREADS;
    constexpr int BN4  = BN / 4;

    __shared__ uint32_t As[2][BM][12];
    __shared__ uint32_t Bs[2][BSR][BSC];

    const int tid = threadIdx.x;
    const int wid = tid >> 5, lane = tid & 31;
    const int g = lane >> 2, tig = lane & 3;
    const int wm0 = (wid / WARPS_N) * WM, wn0 = (wid % WARPS_N) * WN;
    const int nk = K / BK;

    const uint32_t asb = smem_u32(&As[0][0][0]);
    const uint32_t bsb = smem_u32(&Bs[0][0][0]);
    // ldmatrix lane address offsets (bytes) within a 16-row x 16-half block
    const uint32_t aoff_lane = ((lane & 7) + ((lane >> 3) & 1) * 8) * 48u + (uint32_t)(lane >> 4) * 16u;
    const uint32_t boff_lane = ((lane & 7) + ((lane >> 4) & 1) * 8) * 48u + (uint32_t)((lane >> 3) & 1) * 16u;

    for (int T = blockIdx.x; T < ntiles; T += gridDim.x) {
        const int z = T / tpz, tl = T - z * tpz;
        int ty, tx;
        if (band == 0) { ty = tl / tiles_x; tx = tl - ty * tiles_x; }
        else { ty = tl / 5; int rr = tl - ty * 5; tx = (band == 1 ? ty : 3 - ty) + rr; }
        const int m0 = ty * BM, n0 = tx * BN;
        const int bb = z >> 3, hh = z & 7;
        const float* Az = A + (size_t)bb * sAb + (size_t)hh * sAh;
        const float* Bz = B + (size_t)bb * sBb + (size_t)hh * sBh;
        float* Cz = C + (size_t)bb * sCb + (size_t)hh * sCh;
        const float* biasp = bias ? (bias + (size_t)hh * sBiasH) : nullptr;

        float4 abuf[A_IT], bbuf0[B_IT], bbuf1[B_IT];
        float acc[MI][NI][4];
        #pragma unroll
        for (int i = 0; i < MI; i++)
            #pragma unroll
            for (int j = 0; j < NI; j++)
                #pragma unroll
                for (int t = 0; t < 4; t++) acc[i][j][t] = 0.f;

        auto ldgA = [&](int k0) {
            #pragma unroll
            for (int i = 0; i < A_IT; i++) {
                int lin = tid + i * THREADS;
                if ((A_F4 % THREADS == 0) || lin < A_F4) {
                    int m = lin >> 2, c = lin & 3;
                    abuf[i] = *reinterpret_cast<const float4*>(Az + (size_t)(m0 + m) * lda + k0 + 4 * c);
                }
            }
        };
        auto ldgB = [&](int k0) {
            #pragma unroll
            for (int i = 0; i < B_IT; i++) {
                int lin = tid + i * THREADS;
                if ((B_U % THREADS == 0) || lin < B_U) {
                    if (BT) {
                        int n = lin >> 2, c = lin & 3;
                        bbuf0[i] = *reinterpret_cast<const float4*>(Bz + (size_t)(n0 + n) * ldb + k0 + 4 * c);
                    } else {
                        int kk = lin / BN4, c = lin - kk * BN4;
                        const float* p = Bz + (size_t)(k0 + 2 * kk) * ldb + n0 + 4 * c;
                        bbuf0[i] = *reinterpret_cast<const float4*>(p);
                        bbuf1[i] = *reinterpret_cast<const float4*>(p + ldb);
                    }
                }
            }
        };
        auto stsf = [&](int buf) {
            #pragma unroll
            for (int i = 0; i < A_IT; i++) {
                int lin = tid + i * THREADS;
                if ((A_F4 % THREADS == 0) || lin < A_F4) {
                    int m = lin >> 2, c = lin & 3;
                    float4 v = abuf[i];
                    As[buf][m][2 * c]     = packh2(v.x, v.y);
                    As[buf][m][2 * c + 1] = packh2(v.z, v.w);
                }
            }
            #pragma unroll
            for (int i = 0; i < B_IT; i++) {
                int lin = tid + i * THREADS;
                if ((B_U % THREADS == 0) || lin < B_U) {
                    if (BT) {
                        int n = lin >> 2, c = lin & 3;
                        float4 v = bbuf0[i];
                        Bs[buf][n][2 * c]     = packh2(v.x, v.y);
                        Bs[buf][n][2 * c + 1] = packh2(v.z, v.w);
                    } else {
                        int kk = lin / BN4, c = lin - kk * BN4;
                        float4 v0 = bbuf0[i], v1 = bbuf1[i];
                        Bs[buf][kk][4 * c]     = packh2(v0.x, v1.x);
                        Bs[buf][kk][4 * c + 1] = packh2(v0.y, v1.y);
                        Bs[buf][kk][4 * c + 2] = packh2(v0.z, v1.z);
                        Bs[buf][kk][4 * c + 3] = packh2(v0.w, v1.w);
                    }
                }
            }
        };

        ldgA(0); ldgB(0);
        __syncthreads();          // protect smem from previous tile's readers
        stsf(0);
        __syncthreads();
        int cur = 0;
        for (int it = 0; it < nk; it++) {
            if (it + 1 < nk) { ldgA((it + 1) * BK); ldgB((it + 1) * BK); }
            {
                const uint32_t abase = asb + (uint32_t)cur * (BM * 48u) + (uint32_t)wm0 * 48u + aoff_lane;
                uint32_t af[MI][4], bf[NI][2];
                #pragma unroll
                for (int i = 0; i < MI; i++)
                    ldsm_x4(af[i], abase + (uint32_t)i * (16u * 48u));
                if (BT) {
                    const uint32_t bbase = bsb + (uint32_t)cur * (BSR * BSC * 4u) + (uint32_t)wn0 * 48u + boff_lane;
                    #pragma unroll
                    for (int jj = 0; jj < NI / 2; jj++) {
                        uint32_t t4[4];
                        ldsm_x4(t4, bbase + (uint32_t)jj * (16u * 48u));
                        bf[2 * jj][0] = t4[0]; bf[2 * jj][1] = t4[1];
                        bf[2 * jj + 1][0] = t4[2]; bf[2 * jj + 1][1] = t4[3];
                    }
                } else {
                    #pragma unroll
                    for (int j = 0; j < NI; j++) {
                        int cc = wn0 + 8 * j + g;
                        bf[j][0] = Bs[cur][tig    ][cc];
                        bf[j][1] = Bs[cur][tig + 4][cc];
                    }
                }
                #pragma unroll
                for (int i = 0; i < MI; i++)
                    #pragma unroll
                    for (int j = 0; j < NI; j++)
                        mma_f16(acc[i][j], af[i], bf[j]);
            }
            if (it + 1 < nk) { stsf(cur ^ 1); __syncthreads(); cur ^= 1; }
        }

        // epilogue
        #pragma unroll
        for (int i = 0; i < MI; i++) {
            int r0 = m0 + wm0 + 16 * i + g;
            #pragma unroll
            for (int j = 0; j < NI; j++) {
                int col = n0 + wn0 + 8 * j + 2 * tig;
                float b0v = biasp ? biasp[col] : 0.f;
                float b1v = biasp ? biasp[col + 1] : 0.f;
                float v0 = acc[i][j][0] + b0v, v1 = acc[i][j][1] + b1v;
                float v2 = acc[i][j][2] + b0v, v3 = acc[i][j][3] + b1v;
                if (act == 1) { v0 = gelu_f(v0); v1 = gelu_f(v1); v2 = gelu_f(v2); v3 = gelu_f(v3); }
                *reinterpret_cast<float2*>(Cz + (size_t)r0 * ldc + col) = make_float2(v0, v1);
                *reinterpret_cast<float2*>(Cz + (size_t)(r0 + 8) * ldc + col) = make_float2(v2, v3);
            }
        }
    }
}

// ---------------- pack Wq|Wk|Wv -> [L][768][2304], biases -> [L][2304] ----------------
__global__ void pack_qkv(const float* __restrict__ Wq, const float* __restrict__ Wk,
                         const float* __restrict__ Wv, const float* __restrict__ bq,
                         const float* __restrict__ bk, const float* __restrict__ bv,
                         float* __restrict__ W, float* __restrict__ b)
{
    long idx = (long)blockIdx.x * blockDim.x + threadIdx.x;     // float4 units
    const long totW = (long)NLAYER * DMODEL * D3 / 4;
    if (idx < totW) {
        long e = idx * 4;
        int l = (int)(e / ((long)DMODEL * D3));
        long r = e - (long)l * DMODEL * D3;
        int row = (int)(r / D3);
        int col = (int)(r - (long)row * D3);
        const float* src; int c;
        if (col < DMODEL)        { src = Wq; c = col; }
        else if (col < 2*DMODEL) { src = Wk; c = col - DMODEL; }
        else                     { src = Wv; c = col - 2*DMODEL; }
        *reinterpret_cast<float4*>(W + e) =
            *reinterpret_cast<const float4*>(src + ((size_t)l * DMODEL + row) * DMODEL + c);
    }
    if (idx < NLAYER * D3 / 4) {
        long e = idx * 4;
        int l = (int)(e / D3);
        int col = (int)(e - (long)l * D3);
        const float* src; int c;
        if (col < DMODEL)        { src = bq; c = col; }
        else if (col < 2*DMODEL) { src = bk; c = col - DMODEL; }
        else                     { src = bv; c = col - 2*DMODEL; }
        *reinterpret_cast<float4*>(b + e) =
            *reinterpret_cast<const float4*>(src + (size_t)l * DMODEL + c);
    }
}

// -------------------- block reductions (256 threads) --------------------
__device__ __forceinline__ float blk_sum256(float v) {
    __shared__ float sh[8];
    __syncthreads();
    for (int o = 16; o > 0; o >>= 1) v += __shfl_down_sync(0xffffffffu, v, o);
    if ((threadIdx.x & 31) == 0) sh[threadIdx.x >> 5] = v;
    __syncthreads();
    if (threadIdx.x == 0) {
        float s = 0.f;
        #pragma unroll
        for (int i = 0; i < 8; i++) s += sh[i];
        sh[0] = s;
    }
    __syncthreads();
    return sh[0];
}
__device__ __forceinline__ float blk_max256(float v) {
    __shared__ float sh[8];
    __syncthreads();
    for (int o = 16; o > 0; o >>= 1) v = fmaxf(v, __shfl_down_sync(0xffffffffu, v, o));
    if ((threadIdx.x & 31) == 0) sh[threadIdx.x >> 5] = v;
    __syncthreads();
    if (threadIdx.x == 0) {
        float s = sh[0];
        #pragma unroll
        for (int i = 1; i < 8; i++) s = fmaxf(s, sh[i]);
        sh[0] = s;
    }
    __syncthreads();
    return sh[0];
}

// ------------- combine rel-pos biases + mask + softmax (in place over s1) -----------
__global__ void combine_softmax(float* __restrict__ s1, const float* __restrict__ c2p,
                                const float* __restrict__ p2c, const int* __restrict__ amask)
{
    const int q = blockIdx.x, z = blockIdx.y, b = z >> 3;
    const float inv_scale = 0.05892556509887896f;   // 1/sqrt(288)
    float* srow = s1 + ((size_t)z * SEQ + q) * SEQ;
    const float* crow = c2p + ((size_t)z * SEQ + q) * PPOS;
    const float* pz   = p2c + (size_t)z * SEQ * PPOS;
    const int mq = amask[b * SEQ + q];
    float vals[2];
    #pragma unroll
    for (int i = 0; i < 2; i++) {
        int k = threadIdx.x + i * 256;
        int d = q - k + SPAN;
        float s = (srow[k] + crow[d] + pz[(size_t)k * PPOS + d]) * inv_scale;
        int mk = amask[b * SEQ + k];
        vals[i] = (mq * mk > 0) ? s : NEGF;
    }
    float mx = blk_max256(fmaxf(vals[0], vals[1]));
    float e0 = __expf(vals[0] - mx), e1 = __expf(vals[1] - mx);
    float inv = 1.0f / blk_sum256(e0 + e1);
    srow[threadIdx.x]       = e0 * inv;
    srow[threadIdx.x + 256] = e1 * inv;
}

// ---------------- LayerNorm variants ----------------
__global__ void embed_ln(const float* __restrict__ x, const float* __restrict__ pos,
                         const float* __restrict__ g, const float* __restrict__ beta,
                         const int* __restrict__ amask, float* __restrict__ out)
{
    const int row = blockIdx.x, s = row & (SEQ - 1);
    float v[3], partial = 0.f;
    #pragma unroll
    for (int i = 0; i < 3; i++) {
        int j = threadIdx.x + i * 256;
        v[i] = x[(size_t)row * DMODEL + j] + pos[(size_t)s * DMODEL + j];
        partial += v[i];
    }
    float mean = blk_sum256(partial) * (1.0f / DMODEL);
    float p2 = 0.f;
    #pragma unroll
    for (int i = 0; i < 3; i++) { float d = v[i] - mean; p2 += d * d; }
    float rstd = rsqrtf(blk_sum256(p2) * (1.0f / DMODEL) + LN_EPS);
    float mf = (float)amask[row];
    #pragma unroll
    for (int i = 0; i < 3; i++) {
        int j = threadIdx.x + i * 256;
        out[(size_t)row * DMODEL + j] = ((v[i] - mean) * rstd * g[j] + beta[j]) * mf;
    }
}

__global__ void add_ln(const float* __restrict__ a, const float* __restrict__ res,
                       const float* __restrict__ g, const float* __restrict__ beta,
                       float* __restrict__ out)
{
    const int row = blockIdx.x;
    float v[3], partial = 0.f;
    #pragma unroll
    for (int i = 0; i < 3; i++) {
        int j = threadIdx.x + i * 256;
        v[i] = a[(size_t)row * DMODEL + j] + res[(size_t)row * DMODEL + j];
        partial += v[i];
    }
    float mean = blk_sum256(partial) * (1.0f / DMODEL);
    float p2 = 0.f;
    #pragma unroll
    for (int i = 0; i < 3; i++) { float d = v[i] - mean; p2 += d * d; }
    float rstd = rsqrtf(blk_sum256(p2) * (1.0f / DMODEL) + LN_EPS);
    #pragma unroll
    for (int i = 0; i < 3; i++) {
        int j = threadIdx.x + i * 256;
        out[(size_t)row * DMODEL + j] = (v[i] - mean) * rstd * g[j] + beta[j];
    }
}

// ==================================== launcher ====================================
static inline int pgrid(int tiles, int cap) { return tiles < cap ? tiles : cap; }

extern "C" void kernel_launch(void* const* d_in, const int* in_sizes, int n_in,
                              void* d_out, int out_size)
{
    const float* x       = (const float*)d_in[0];
    const float* pos_emb = (const float*)d_in[1];
    const float* rel_emb = (const float*)d_in[2];
    const float* ln_e_g  = (const float*)d_in[3];
    const float* ln_e_b  = (const float*)d_in[4];
    const float* Wq  = (const float*)d_in[5];
    const float* bq  = (const float*)d_in[6];
    const float* Wk  = (const float*)d_in[7];
    const float* bk  = (const float*)d_in[8];
    const float* Wv  = (const float*)d_in[9];
    const float* bv  = (const float*)d_in[10];
    const float* Wo  = (const float*)d_in[11];
    const float* bo  = (const float*)d_in[12];
    const float* Wpk = (const float*)d_in[13];
    const float* bpk = (const float*)d_in[14];
    const float* Wpq = (const float*)d_in[15];
    const float* bpq = (const float*)d_in[16];
    const float* ln1g = (const float*)d_in[17];
    const float* ln1b = (const float*)d_in[18];
    const float* Wi   = (const float*)d_in[19];
    const float* bi   = (const float*)d_in[20];
    const float* Wo2  = (const float*)d_in[21];
    const float* bo2  = (const float*)d_in[22];
    const float* ln2g = (const float*)d_in[23];
    const float* ln2b = (const float*)d_in[24];
    const int*   amask = (const int*)d_in[25];

    float *h, *qkv, *ctx, *tmp, *wqkv, *bqkv, *pkall, *pqall, *s1, *c2p, *p2c, *ffn;
    cudaGetSymbolAddress((void**)&h,    g_h);
    cudaGetSymbolAddress((void**)&qkv,  g_qkv);
    cudaGetSymbolAddress((void**)&ctx,  g_ctx);
    cudaGetSymbolAddress((void**)&tmp,  g_tmp);
    cudaGetSymbolAddress((void**)&wqkv, g_wqkv);
    cudaGetSymbolAddress((void**)&bqkv, g_bqkv);
    cudaGetSymbolAddress((void**)&pkall, g_pkall);
    cudaGetSymbolAddress((void**)&pqall, g_pqall);
    cudaGetSymbolAddress((void**)&s1,   g_s1);
    cudaGetSymbolAddress((void**)&c2p,  g_c2p);
    cudaGetSymbolAddress((void**)&p2c,  g_p2c);
    cudaGetSymbolAddress((void**)&ffn,  g_ffn);

    const long DD = (long)DMODEL * DMODEL;
    const long S2 = (long)SEQ * SEQ;
    const long SP = (long)SEQ * PPOS;
    const long SD3 = (long)SEQ * D3;
    const long PD = (long)PPOS * DMODEL;
    const int CAP2 = 296;    // 2 CTAs/SM x 148 (256-thread configs)
    const int CAP4 = 592;    // 128-thread config

    // weight packing + embeddings
    {
        long totW4 = (long)NLAYER * DMODEL * D3 / 4;
        pack_qkv<<<(unsigned)((totW4 + 255) / 256), 256>>>(Wq, Wk, Wv, bq, bk, bv, wqkv, bqkv);
    }
    embed_ln<<<NTOK, 256>>>(x, pos_emb, ln_e_g, ln_e_b, amask, h);

    // all-layer position projections (z = layer): 48 tiles/z, 288 total
    mma_gemm<128,128,16,64,32,8,false><<<pgrid(288, CAP2), 256>>>(
        rel_emb, Wpk, bpk, pkall, DMODEL, DMODEL, DMODEL, DMODEL,
        0, 0, 0, DD, DMODEL, 0, PD, 0, 288, 48, 6, 0);
    mma_gemm<128,128,16,64,32,8,false><<<pgrid(288, CAP2), 256>>>(
        rel_emb, Wpq, bpq, pqall, DMODEL, DMODEL, DMODEL, DMODEL,
        0, 0, 0, DD, DMODEL, 0, PD, 0, 288, 48, 6, 0);

    for (int l = 0; l < NLAYER; l++) {
        // fused QKV: 32x18 = 576 tiles
        mma_gemm<128,128,16,64,32,8,false><<<pgrid(576, CAP2), 256>>>(
            h, wqkv + (size_t)l * DMODEL * D3, bqkv + (size_t)l * D3, qkv,
            DMODEL, DMODEL, D3, D3, 0,0,0,0,0, 0,0, 0, 576, 576, 18, 0);

        // scores = Q @ K^T : 16 tiles/z * 64
        mma_gemm<128,128,16,64,32,8,true><<<pgrid(1024, CAP2), 256>>>(
            qkv, qkv + DMODEL, nullptr, s1, DH, D3, D3, SEQ,
            SD3, DH, SD3, DH, 0, 8*S2, S2, 0, 1024, 16, 4, 0);
        // c2p = Q @ PK^T (banded: 20 tiles/z)
        mma_gemm<128,128,16,64,32,8,true><<<pgrid(1280, CAP2), 256>>>(
            qkv, pkall + (size_t)l * PD, nullptr, c2p, DH, D3, DMODEL, PPOS,
            SD3, DH, 0, DH, 0, 8*SP, SP, 0, 1280, 20, 0, 1);
        // p2c = K @ PQ^T (banded)
        mma_gemm<128,128,16,64,32,8,true><<<pgrid(1280, CAP2), 256>>>(
            qkv + DMODEL, pqall + (size_t)l * PD, nullptr, p2c, DH, D3, DMODEL, PPOS,
            SD3, DH, 0, DH, 0, 8*SP, SP, 0, 1280, 20, 0, 2);

        combine_softmax<<<dim3(SEQ, ZBAT), 256>>>(s1, c2p, p2c, amask);

        // ctx = probs @ V -> [b, q, h*96+d] ; 4 tiles/z * 64 = 256
        mma_gemm<128,96,16,64,32,6,false><<<pgrid(256, CAP2), 192>>>(
            s1, qkv + 2*DMODEL, nullptr, ctx, SEQ, SEQ, D3, DMODEL,
            8*S2, S2, SD3, DH, 0, (long)SEQ*DMODEL, DH, 0, 256, 4, 1, 0);

        // attn out proj: 64x128 tiles -> 384 tiles
        mma_gemm<64,128,16,64,32,4,false><<<pgrid(384, CAP4), 128>>>(
            ctx, Wo + (size_t)l*DD, bo + (size_t)l*DMODEL, tmp,
            DMODEL, DMODEL, DMODEL, DMODEL, 0,0,0,0,0, 0,0, 0, 384, 384, 6, 0);
        add_ln<<<NTOK, 256>>>(tmp, h, ln1g + (size_t)l*DMODEL, ln1b + (size_t)l*DMODEL, h);

        // FFN1 (gelu): 768 tiles
        mma_gemm<128,128,16,64,32,8,false><<<pgrid(768, CAP2), 256>>>(
            h, Wi + (size_t)l*DMODEL*FF, bi + (size_t)l*FF, ffn,
            DMODEL, DMODEL, FF, FF, 0,0,0,0,0, 0,0, 1, 768, 768, 24, 0);
        // FFN2: K=3072, 384 tiles
        mma_gemm<64,128,16,64,32,4,false><<<pgrid(384, CAP4), 128>>>(
            ffn, Wo2 + (size_t)l*FF*DMODEL, bo2 + (size_t)l*DMODEL, tmp,
            FF, FF, DMODEL, DMODEL, 0,0,0,0,0, 0,0, 0, 384, 384, 6, 0);

        float* outp = (l == NLAYER - 1) ? (float*)d_out : h;
        add_ln<<<NTOK, 256>>>(tmp, h, ln2g + (size_t)l*DMODEL, ln2b + (size_t)l*DMODEL, outp);
    }
}